// round 15
// baseline (speedup 1.0000x reference)
#include <cuda_runtime.h>
#include <cuda_bf16.h>
#include <math.h>

#define SEQ   2048
#define DMOD  1024
#define DIN   2048
#define NHEAD 8
#define DHEAD 256
#define DHID  2048

typedef __nv_bfloat16 bf16;

// ---------------- scratch (allocation-free: __device__ globals) ----------------
__device__ float g_ig  [NHEAD*SEQ];
__device__ float g_fg  [NHEAD*SEQ];
__device__ float g_rowt[NHEAD*SEQ];
__device__ float g_colt[NHEAD*SEQ];
__device__ float g_expn[NHEAD*SEQ];
__device__ float g_psum[NHEAD*16*SEQ];
__device__ float g_hfl [SEQ*DIN];
__device__ float g_hfl2[SEQ*DIN];
__device__ float g_x2  [SEQ*DMOD];
__device__ float g_sk0 [SEQ*DMOD];
__device__ float g_sk1 [SEQ*DMOD];

__device__ bf16 g_hln_bf [SEQ*DMOD];
__device__ bf16 g_proj_bf[SEQ*2*DIN];
__device__ bf16 g_xc_bf  [SEQ*DIN];
__device__ bf16 g_q_bf   [SEQ*DIN];
__device__ bf16 g_k_bf   [SEQ*DIN];
__device__ bf16 g_v_bf   [SEQ*DIN];
__device__ bf16 g_vt_bf  [(size_t)NHEAD*DHEAD*SEQ];
__device__ bf16 g_C_bf   [(size_t)NHEAD*SEQ*SEQ];
__device__ bf16 g_yin_bf [SEQ*DIN];
__device__ bf16 g_hf_bf  [SEQ*DMOD];
__device__ bf16 g_g2_bf  [SEQ*DHID];
__device__ bf16 g_winw_bf[2*DIN*DMOD];
__device__ bf16 g_woutw_bf[DMOD*DIN];
__device__ bf16 g_ffnw_bf[2*DHID*DMOD];   // ROW-REORDERED: row 2t = a-row t, row 2t+1 = z-row DHID+t
__device__ bf16 g_ffnow_bf[DMOD*DHID];
__device__ bf16 g_wqt_bf[NHEAD*DHEAD*DHEAD];
__device__ bf16 g_wkt_bf[NHEAD*DHEAD*DHEAD];
__device__ bf16 g_wvt_bf[NHEAD*DHEAD*DHEAD];

// ---------------- tile config ----------------
#define BM 128
#define BN 128
#define BKB 64                   // bf16 elements per stage (128B rows)
#define TILEB 16384              // 128 rows x 128B
#define SMEM_GEMM (6*TILEB)      // triple-buffered A+B = 96KB

__device__ __forceinline__ unsigned sw128(unsigned o){ return o ^ ((o>>3)&0x70); }

__device__ __forceinline__ void cp16(void* smem_dst, const void* gsrc){
    unsigned s = (unsigned)__cvta_generic_to_shared(smem_dst);
    asm volatile("cp.async.cg.shared.global [%0], [%1], 16;" :: "r"(s), "l"(gsrc));
}
#define CP_COMMIT() asm volatile("cp.async.commit_group;")
#define CP_WAIT(n)  asm volatile("cp.async.wait_group %0;" :: "n"(n))

__device__ __forceinline__ void ldsm4(unsigned r[4], const void* p){
    unsigned a = (unsigned)__cvta_generic_to_shared(p);
    asm volatile("ldmatrix.sync.aligned.m8n8.x4.shared.b16 {%0,%1,%2,%3}, [%4];"
        : "=r"(r[0]),"=r"(r[1]),"=r"(r[2]),"=r"(r[3]) : "r"(a));
}

#define MMA_BF16(d, a, b) \
  asm volatile("mma.sync.aligned.m16n8k16.row.col.f32.bf16.bf16.f32 " \
    "{%0,%1,%2,%3},{%4,%5,%6,%7},{%8,%9},{%0,%1,%2,%3};" \
    : "+f"((d)[0]),"+f"((d)[1]),"+f"((d)[2]),"+f"((d)[3]) \
    : "r"((a)[0]),"r"((a)[1]),"r"((a)[2]),"r"((a)[3]),"r"((b)[0]),"r"((b)[1]))

__device__ __forceinline__ float ftanh(float x){
    float y; asm("tanh.approx.f32 %0, %1;" : "=f"(y) : "f"(x)); return y;
}
__device__ __forceinline__ float fsigmoid(float x){ return 1.f / (1.f + __expf(-x)); }
__device__ __forceinline__ float fgelu(float a){
    float t = ftanh(0.7978845608028654f * (a + 0.044715f*a*a*a));
    return 0.5f * a * (1.f + t);
}

__device__ __forceinline__ void stage_bf(const bf16* __restrict__ src, int ld,
      int row0, int k0, char* S, int tid)
{
#pragma unroll
    for (int it=0; it<4; it++){
        int idx = it*256 + tid;
        int r = idx>>3, ch = idx&7;
        cp16(S + sw128(r*128 + ch*16), src + (size_t)(row0+r)*ld + k0 + ch*8);
    }
}

__device__ __forceinline__ void compute_bf(const char* __restrict__ As,
    const char* __restrict__ Bs, float acc[4][4][4], int lane, int wm, int wn)
{
    const int l15 = lane&15, lh = lane>>4, l7 = lane&7, lb3 = (lane>>3)&1;
#pragma unroll
    for (int kk=0;kk<4;kk++){
        unsigned a[4][4];
#pragma unroll
        for (int mt=0;mt<4;mt++)
            ldsm4(a[mt], As + sw128((wm + mt*16 + l15)*128 + (kk*2 + lh)*16));
        unsigned b[2][4];
#pragma unroll
        for (int bp=0;bp<2;bp++){
            unsigned row = wn + bp*16 + lh*8 + l7;
            ldsm4(b[bp], Bs + sw128(row*128 + (kk*2 + lb3)*16));
        }
#pragma unroll
        for (int mt=0;mt<4;mt++)
#pragma unroll
            for (int nt=0;nt<4;nt++)
                MMA_BF16(acc[mt][nt], a[mt], b[nt>>1] + (nt&1)*2);
    }
}

// 3-stage cp.async pipeline, one barrier per K-step
__device__ __forceinline__ void gemm_loop_bf(const bf16* __restrict__ A, int lda,
    const bf16* __restrict__ B, int ldb, int m0, int n0, int K,
    char* smem, float acc[4][4][4], int tid, int lane, int wm, int wn)
{
    const int nsteps = K >> 6;
    stage_bf(A, lda, m0, 0, smem, tid);
    stage_bf(B, ldb, n0, 0, smem + TILEB, tid);
    CP_COMMIT();
    if (nsteps > 1){
        stage_bf(A, lda, m0, BKB, smem + 2*TILEB, tid);
        stage_bf(B, ldb, n0, BKB, smem + 3*TILEB, tid);
        CP_COMMIT();
    }
    for (int s=0; s<nsteps; s++){
        if (s+1 < nsteps) { CP_WAIT(1); } else { CP_WAIT(0); }
        __syncthreads();
        if (s+2 < nsteps){
            char* T = smem + ((s+2)%3)*2*TILEB;
            stage_bf(A, lda, m0, (s+2)*BKB, T, tid);
            stage_bf(B, ldb, n0, (s+2)*BKB, T + TILEB, tid);
            CP_COMMIT();
        }
        char* Cur = smem + (s%3)*2*TILEB;
        compute_bf(Cur, Cur + TILEB, acc, lane, wm, wn);
    }
    __syncthreads();   // smem safe for reuse after loop
}

// ---------------- GEMM kernels ----------------

// C[m,n] = sum_k A[m,k]*B[n,k] (+bias) (+resid); optional fp32 out, optional bf16 out
__global__ __launch_bounds__(256, 2) void mma_nt_bf(
    const bf16* __restrict__ A, const bf16* __restrict__ B,
    const float* __restrict__ bias, const float* __restrict__ resid,
    float* __restrict__ Cf, bf16* __restrict__ Cb,
    int K, int lda, int ldb, int ldc, int ldr, int ldcb)
{
    extern __shared__ char smem[];
    const int tid=threadIdx.x, lane=tid&31, wid=tid>>5;
    const int wm=(wid>>2)*64, wn=(wid&3)*32;
    const int m0=blockIdx.y*BM, n0=blockIdx.x*BN;
    float acc[4][4][4] = {};
    gemm_loop_bf(A, lda, B, ldb, m0, n0, K, smem, acc, tid, lane, wm, wn);
    const int gr=lane>>2, gc=lane&3;
#pragma unroll
    for (int mt=0;mt<4;mt++){
#pragma unroll
        for (int nt=0;nt<4;nt++){
            int row = m0+wm+mt*16+gr;
            int col = n0+wn+nt*8+gc*2;
            float b0=0.f,b1=0.f;
            if (bias){ b0=bias[col]; b1=bias[col+1]; }
            float r00=0,r01=0,r10=0,r11=0;
            if (resid){
                const float* rp  = resid + (size_t)row*ldr + col;
                const float* rp2 = resid + (size_t)(row+8)*ldr + col;
                r00=rp[0]; r01=rp[1]; r10=rp2[0]; r11=rp2[1];
            }
            float v00=acc[mt][nt][0]+b0+r00, v01=acc[mt][nt][1]+b1+r01;
            float v10=acc[mt][nt][2]+b0+r10, v11=acc[mt][nt][3]+b1+r11;
            if (Cf){
                *(float2*)(Cf + (size_t)row*ldc + col)     = make_float2(v00,v01);
                *(float2*)(Cf + (size_t)(row+8)*ldc + col) = make_float2(v10,v11);
            }
            if (Cb){
                *(__nv_bfloat162*)(Cb + (size_t)row*ldcb + col)     = __floats2bfloat162_rn(v00,v01);
                *(__nv_bfloat162*)(Cb + (size_t)(row+8)*ldcb + col) = __floats2bfloat162_rn(v10,v11);
            }
        }
    }
}

// split-K NT GEMM: kidx = blockIdx.z + kbase selects K-half and output buffer
__global__ __launch_bounds__(256, 2) void mma_nt_sk(
    const bf16* __restrict__ A, const bf16* __restrict__ B,
    int Khalf, int lda, int ldb, int kbase)
{
    extern __shared__ char smem[];
    const int tid=threadIdx.x, lane=tid&31, wid=tid>>5;
    const int wm=(wid>>2)*64, wn=(wid&3)*32;
    const int m0=blockIdx.y*BM, n0=blockIdx.x*BN;
    const int kidx = blockIdx.z + kbase;
    const int koff = kidx * Khalf;
    float* P = kidx ? g_sk1 : g_sk0;
    float acc[4][4][4] = {};
    gemm_loop_bf(A + koff, lda, B + koff, ldb, m0, n0, Khalf, smem, acc, tid, lane, wm, wn);
    const int gr=lane>>2, gc=lane&3;
#pragma unroll
    for (int mt=0;mt<4;mt++){
#pragma unroll
        for (int nt=0;nt<4;nt++){
            int row = m0+wm+mt*16+gr;
            int col = n0+wn+nt*8+gc*2;
            *(float2*)(P + (size_t)row*DMOD + col)     = make_float2(acc[mt][nt][0],acc[mt][nt][1]);
            *(float2*)(P + (size_t)(row+8)*DMOD + col) = make_float2(acc[mt][nt][2],acc[mt][nt][3]);
        }
    }
}

// ffn-in GEMM with fused GELU-pair epilogue (interleaved weights); n0base selects N-half.
__global__ __launch_bounds__(256, 2) void mma_ffn1(int n0base)
{
    extern __shared__ char smem[];
    const int tid=threadIdx.x, lane=tid&31, wid=tid>>5;
    const int wm=(wid>>2)*64, wn=(wid&3)*32;
    const int m0=blockIdx.y*BM, n0=(blockIdx.x + n0base)*BN;
    float acc[4][4][4] = {};
    gemm_loop_bf(g_hf_bf, DMOD, g_ffnw_bf, DMOD, m0, n0, DMOD, smem, acc, tid, lane, wm, wn);
    const int gr=lane>>2, gc=lane&3;
#pragma unroll
    for (int mt=0;mt<4;mt++){
#pragma unroll
        for (int nt=0;nt<4;nt++){
            int row = m0+wm+mt*16+gr;
            int col = n0+wn+nt*8+gc*2;   // even: a, odd: z
            int t = col >> 1;
            g_g2_bf[(size_t)row*DHID + t]     = __float2bfloat16_rn(fgelu(acc[mt][nt][0]) * acc[mt][nt][1]);
            g_g2_bf[(size_t)(row+8)*DHID + t] = __float2bfloat16_rn(fgelu(acc[mt][nt][2]) * acc[mt][nt][3]);
        }
    }
}

// fused q/k/v with z-base: z = blockIdx.z + zbase; which = z>>3 (0=q,1=k,2=v)
__global__ __launch_bounds__(256, 2) void mma_qkv(int zbase)
{
    const int z = blockIdx.z + zbase;
    const int which = z >> 3;
    const int h = z & 7;
    const bf16* A; int lda; const bf16* B; bf16* C;
    if (which == 0){ A = g_xc_bf   + h*DHEAD; lda = DIN;   B = g_wqt_bf + h*DHEAD*DHEAD; C = g_q_bf + h*DHEAD; }
    else if (which == 1){ A = g_xc_bf + h*DHEAD; lda = DIN; B = g_wkt_bf + h*DHEAD*DHEAD; C = g_k_bf + h*DHEAD; }
    else { A = g_proj_bf + h*DHEAD; lda = 2*DIN; B = g_wvt_bf + h*DHEAD*DHEAD; C = g_v_bf + h*DHEAD; }
    extern __shared__ char smem[];
    const int tid=threadIdx.x, lane=tid&31, wid=tid>>5;
    const int wm=(wid>>2)*64, wn=(wid&3)*32;
    const int m0=blockIdx.y*BM, n0=blockIdx.x*BN;
    float acc[4][4][4] = {};
    gemm_loop_bf(A, lda, B, DHEAD, m0, n0, DHEAD, smem, acc, tid, lane, wm, wn);
    const int gr=lane>>2, gc=lane&3;
#pragma unroll
    for (int mt=0;mt<4;mt++){
#pragma unroll
        for (int nt=0;nt<4;nt++){
            int row = m0+wm+mt*16+gr;
            int col = n0+wn+nt*8+gc*2;
            *(__nv_bfloat162*)(C + (size_t)row*DIN + col)     = __floats2bfloat162_rn(acc[mt][nt][0],acc[mt][nt][1]);
            *(__nv_bfloat162*)(C + (size_t)(row+8)*DIN + col) = __floats2bfloat162_rn(acc[mt][nt][2],acc[mt][nt][3]);
        }
    }
}

// scores: C[h][l,m] = (q·k)/16 * exp(rowt[l]+colt[m]) masked; bf16 out + fp32 tile row-sums
__global__ __launch_bounds__(256, 2) void mma_score_bf()
{
    const int h  = blockIdx.z;
    const int l0 = blockIdx.y * BM;
    const int m0 = blockIdx.x * BN;
    if (m0 >= l0 + BM) return;   // fully-masked tile: skipped (never read downstream)
    extern __shared__ char smem[];
    const bf16* A = g_q_bf + h*DHEAD;
    const bf16* B = g_k_bf + h*DHEAD;
    const int tid=threadIdx.x, lane=tid&31, wid=tid>>5;
    const int wm=(wid>>2)*64, wn=(wid&3)*32;
    float acc[4][4][4] = {};
    gemm_loop_bf(A, DIN, B, DIN, l0, m0, DHEAD, smem, acc, tid, lane, wm, wn);

    float* sred = (float*)smem;   // safe: gemm_loop ends with syncthreads
    const float* rt = g_rowt + h*SEQ;
    const float* ct = g_colt + h*SEQ;
    bf16* Cb = g_C_bf + (size_t)h*SEQ*SEQ;
    const int gr=lane>>2, gc=lane&3;
#pragma unroll
    for (int mt=0;mt<4;mt++){
        int l = l0+wm+mt*16+gr;
        float rl0 = rt[l], rl1 = rt[l+8];
        float rs0 = 0.f, rs1 = 0.f;
#pragma unroll
        for (int nt=0;nt<4;nt++){
            int m = m0+wn+nt*8+gc*2;
            float cm0 = ct[m], cm1 = ct[m+1];
            float v00 = (m   <= l  ) ? acc[mt][nt][0]*0.0625f*__expf(rl0+cm0) : 0.f;
            float v01 = (m+1 <= l  ) ? acc[mt][nt][1]*0.0625f*__expf(rl0+cm1) : 0.f;
            float v10 = (m   <= l+8) ? acc[mt][nt][2]*0.0625f*__expf(rl1+cm0) : 0.f;
            float v11 = (m+1 <= l+8) ? acc[mt][nt][3]*0.0625f*__expf(rl1+cm1) : 0.f;
            rs0 += v00 + v01;
            rs1 += v10 + v11;
            *(__nv_bfloat162*)(Cb + (size_t)l*SEQ + m)     = __floats2bfloat162_rn(v00,v01);
            *(__nv_bfloat162*)(Cb + (size_t)(l+8)*SEQ + m) = __floats2bfloat162_rn(v10,v11);
        }
        rs0 += __shfl_xor_sync(0xffffffffu, rs0, 1);
        rs0 += __shfl_xor_sync(0xffffffffu, rs0, 2);
        rs1 += __shfl_xor_sync(0xffffffffu, rs1, 1);
        rs1 += __shfl_xor_sync(0xffffffffu, rs1, 2);
        if (gc == 0){
            sred[(wm+mt*16+gr)*4   + (wid&3)] = rs0;
            sred[(wm+mt*16+gr+8)*4 + (wid&3)] = rs1;
        }
    }
    __syncthreads();
    if (tid < 128){
        float s = sred[tid*4] + sred[tid*4+1] + sred[tid*4+2] + sred[tid*4+3];
        g_psum[((size_t)h*16 + blockIdx.x)*SEQ + l0 + tid] = s;
    }
}

// hflat partials (split-K over the causal range): grid.z = sp*NHEAD + h
__global__ __launch_bounds__(256, 2) void mma_pav_bf()
{
    const int z  = blockIdx.z;
    const int sp = z >> 3;
    const int h  = z & 7;
    const int l0 = blockIdx.y * BM;
    const int n0 = blockIdx.x * BN;
    extern __shared__ char smem[];
    __shared__ float inrm_s[BM];
    const int tid=threadIdx.x, lane=tid&31, wid=tid>>5;
    if (tid < BM){
        int l = l0 + tid;
        int ntl = (l >> 7) + 1;
        float s = 0.f;
        for (int t=0; t<ntl; t++) s += g_psum[((size_t)h*16 + t)*SEQ + l];
        float n = fmaxf(fabsf(s), g_expn[h*SEQ + l]) + 1e-6f;
        inrm_s[tid] = 1.0f / n;
    }
    const int Kmax  = l0 + BM;
    const int Khalf = Kmax >> 1;
    const int k0 = sp ? Khalf : 0;
    const int Klen = sp ? (Kmax - Khalf) : Khalf;
    const bf16* A = g_C_bf + (size_t)h*SEQ*SEQ + k0;
    const bf16* B = g_vt_bf + (size_t)h*DHEAD*SEQ + k0;
    float* OUT = sp ? g_hfl2 : g_hfl;
    const int wm=(wid>>2)*64, wn=(wid&3)*32;
    float acc[4][4][4] = {};
    gemm_loop_bf(A, SEQ, B, SEQ, l0, n0, Klen, smem, acc, tid, lane, wm, wn);
    const int gr=lane>>2, gc=lane&3;
#pragma unroll
    for (int mt=0;mt<4;mt++){
#pragma unroll
        for (int nt=0;nt<4;nt++){
            int lr = wm+mt*16+gr;
            int l = l0+lr;
            int col = n0+wn+nt*8+gc*2;
            float s0 = inrm_s[lr];
            float s1 = inrm_s[lr+8];
            float* c0 = OUT + (size_t)l*DIN + h*DHEAD + col;
            float* c1 = OUT + (size_t)(l+8)*DIN + h*DHEAD + col;
            *(float2*)c0 = make_float2(acc[mt][nt][0]*s0, acc[mt][nt][1]*s0);
            *(float2*)c1 = make_float2(acc[mt][nt][2]*s1, acc[mt][nt][3]*s1);
        }
    }
}

// ---------------- weight prep ----------------
#define CW_N0 524288
#define CW_N1 262144
#define CW_N2 262144
#define CW_N3 524288
__device__ __forceinline__ void cvt8(const float* s, bf16* d){
    float4 a = ((const float4*)s)[0], b = ((const float4*)s)[1];
    __nv_bfloat162 o[4] = { __floats2bfloat162_rn(a.x,a.y), __floats2bfloat162_rn(a.z,a.w),
                            __floats2bfloat162_rn(b.x,b.y), __floats2bfloat162_rn(b.z,b.w) };
    *(uint4*)d = *(uint4*)o;
}
__global__ void convert_winw(const float* __restrict__ winw)
{
    int i = blockIdx.x*256 + threadIdx.x;
    if (i < CW_N0) cvt8(winw + (size_t)i*8, g_winw_bf + (size_t)i*8);
}
__global__ void convert_rest(const float* __restrict__ woutw,
                             const float* __restrict__ ffnw, const float* __restrict__ ffnow)
{
    int i = blockIdx.x*256 + threadIdx.x;
    if (i < CW_N1){
        cvt8(woutw + (size_t)i*8, g_woutw_bf + (size_t)i*8);
    } else if (i < CW_N1+CW_N2){
        int j = i - CW_N1;
        cvt8(ffnow + (size_t)j*8, g_ffnow_bf + (size_t)j*8);
    } else {
        int j = i - CW_N1 - CW_N2;
        if (j < CW_N3){
            int r = j >> 7, c8 = (j & 127) * 8;
            int src = (r & 1) ? (DHID + (r>>1)) : (r>>1);
            cvt8(ffnw + (size_t)src*DMOD + c8, g_ffnw_bf + (size_t)r*DMOD + c8);
        }
    }
}

__global__ void transpose_w_all(const float* __restrict__ wq, const float* __restrict__ wk,
                                const float* __restrict__ wv)
{
    __shared__ float t[32][33];
    int z = blockIdx.z;
    int which = z >> 3, h = z & 7;
    const float* I = (which==0 ? wq : which==1 ? wk : wv) + (size_t)h*DHEAD*DHEAD;
    bf16* O = (which==0 ? g_wqt_bf : which==1 ? g_wkt_bf : g_wvt_bf) + (size_t)h*DHEAD*DHEAD;
    int k0 = blockIdx.y*32, d0 = blockIdx.x*32;
    int x = threadIdx.x, y = threadIdx.y;
#pragma unroll
    for (int i=0;i<32;i+=8) t[y+i][x] = I[(size_t)(k0+y+i)*DHEAD + d0 + x];
    __syncthreads();
#pragma unroll
    for (int i=0;i<32;i+=8) O[(size_t)(d0+y+i)*DHEAD + k0 + x] = __float2bfloat16_rn(t[x][y+i]);
}

__global__ void transpose_v_bf()
{
    __shared__ float t[32][33];
    int h = blockIdx.z;
    int m0 = blockIdx.x*32, d0 = blockIdx.y*32;
    int x = threadIdx.x, y = threadIdx.y;
#pragma unroll
    for (int i=0;i<32;i+=8) t[y+i][x] = __bfloat162float(g_v_bf[(size_t)(m0+y+i)*DIN + h*DHEAD + d0 + x]);
    __syncthreads();
#pragma unroll
    for (int i=0;i<32;i+=8)
        g_vt_bf[((size_t)h*DHEAD + d0+y+i)*SEQ + m0 + x] = __float2bfloat16_rn(t[x][y+i]);
}

// ---------------- elementwise / reduction kernels ----------------
__global__ __launch_bounds__(256) void layernorm_bf(const float* __restrict__ x,
    const float* __restrict__ w, bf16* __restrict__ out, int cols)
{
    int wrp = threadIdx.x >> 5, lane = threadIdx.x & 31;
    int row = blockIdx.x*8 + wrp;
    const float* xr = x + (size_t)row*cols;
    float4 v[8];
    float s = 0.f, ss = 0.f;
#pragma unroll
    for (int i=0;i<8;i++){
        v[i] = ((const float4*)xr)[lane + i*32];
        s  += v[i].x + v[i].y + v[i].z + v[i].w;
        ss += v[i].x*v[i].x + v[i].y*v[i].y + v[i].z*v[i].z + v[i].w*v[i].w;
    }
#pragma unroll
    for (int off=16; off>0; off>>=1){
        s  += __shfl_xor_sync(0xffffffffu, s,  off);
        ss += __shfl_xor_sync(0xffffffffu, ss, off);
    }
    float mean = s / cols;
    float var  = ss / cols - mean*mean;
    float rstd = rsqrtf(var + 1e-5f);
    bf16* orow = out + (size_t)row*cols;
#pragma unroll
    for (int i=0;i<8;i++){
        float4 wv = ((const float4*)w)[lane + i*32];
        __nv_bfloat162 o0 = __floats2bfloat162_rn((v[i].x-mean)*rstd*wv.x, (v[i].y-mean)*rstd*wv.y);
        __nv_bfloat162 o1 = __floats2bfloat162_rn((v[i].z-mean)*rstd*wv.z, (v[i].w-mean)*rstd*wv.w);
        uint2 pk = make_uint2(*(unsigned*)&o0, *(unsigned*)&o1);
        *(uint2*)(orow + (lane + i*32)*4) = pk;
    }
}

// x2 = x + P0 + P1; hf = LN(x2)*w (split-K combine + LN fused)
__global__ __launch_bounds__(256) void ln_combine(const float* __restrict__ x,
    const float* __restrict__ w, bf16* __restrict__ out, float* __restrict__ x2)
{
    const int cols = DMOD;
    int wrp = threadIdx.x >> 5, lane = threadIdx.x & 31;
    int row = blockIdx.x*8 + wrp;
    const float* xr = x + (size_t)row*cols;
    const float* p0 = g_sk0 + (size_t)row*cols;
    const float* p1 = g_sk1 + (size_t)row*cols;
    float4 v[8];
    float s = 0.f, ss = 0.f;
#pragma unroll
    for (int i=0;i<8;i++){
        float4 a = ((const float4*)xr)[lane + i*32];
        float4 b = ((const float4*)p0)[lane + i*32];
        float4 c = ((const float4*)p1)[lane + i*32];
        v[i] = make_float4(a.x+b.x+c.x, a.y+b.y+c.y, a.z+b.z+c.z, a.w+b.w+c.w);
        s  += v[i].x + v[i].y + v[i].z + v[i].w;
        ss += v[i].x*v[i].x + v[i].y*v[i].y + v[i].z*v[i].z + v[i].w*v[i].w;
    }
#pragma unroll
    for (int off=16; off>0; off>>=1){
        s  += __shfl_xor_sync(0xffffffffu, s,  off);
        ss += __shfl_xor_sync(0xffffffffu, ss, off);
    }
    float mean = s / cols;
    float var  = ss / cols - mean*mean;
    float rstd = rsqrtf(var + 1e-5f);
    bf16* orow = out + (size_t)row*cols;
    float* x2r = x2 + (size_t)row*cols;
#pragma unroll
    for (int i=0;i<8;i++){
        ((float4*)x2r)[lane + i*32] = v[i];
        float4 wv = ((const float4*)w)[lane + i*32];
        __nv_bfloat162 o0 = __floats2bfloat162_rn((v[i].x-mean)*rstd*wv.x, (v[i].y-mean)*rstd*wv.y);
        __nv_bfloat162 o1 = __floats2bfloat162_rn((v[i].z-mean)*rstd*wv.z, (v[i].w-mean)*rstd*wv.w);
        uint2 pk = make_uint2(*(unsigned*)&o0, *(unsigned*)&o1);
        *(uint2*)(orow + (lane + i*32)*4) = pk;
    }
}

__global__ void final_combine(float* __restrict__ out)
{
    int i = blockIdx.x*256 + threadIdx.x;
    if (i >= SEQ*DMOD/4) return;
    float4 a = ((const float4*)g_x2)[i];
    float4 b = ((const float4*)g_sk0)[i];
    float4 c = ((const float4*)g_sk1)[i];
    ((float4*)out)[i] = make_float4(a.x+b.x+c.x, a.y+b.y+c.y, a.z+b.z+c.z, a.w+b.w+c.w);
}

__global__ __launch_bounds__(256) void conv_silu_kernel(const float* __restrict__ ck, const float* __restrict__ cb)
{
    int l = blockIdx.x;
    int c8 = threadIdx.x * 8;
    float acc[8];
    {
        float4 b0 = *(const float4*)(cb + c8);
        float4 b1 = *(const float4*)(cb + c8 + 4);
        acc[0]=b0.x; acc[1]=b0.y; acc[2]=b0.z; acc[3]=b0.w;
        acc[4]=b1.x; acc[5]=b1.y; acc[6]=b1.z; acc[7]=b1.w;
    }
    float4 kt[8];
#pragma unroll
    for (int j=0;j<8;j++) kt[j] = *(const float4*)(ck + (c8+j)*4);
#pragma unroll
    for (int t=0;t<4;t++){
        int ls = l - t;
        if (ls < 0) break;
        uint4 u = *(const uint4*)(g_proj_bf + (size_t)ls*(2*DIN) + c8);
        __nv_bfloat162* bp = (__nv_bfloat162*)&u;
        float tap[8];
#pragma unroll
        for (int j=0;j<4;j++){ float2 f = __bfloat1622float2(bp[j]); tap[2*j]=f.x; tap[2*j+1]=f.y; }
#pragma unroll
        for (int j=0;j<8;j++)
            acc[j] = fmaf(tap[j], ((float*)&kt[j])[t], acc[j]);
    }
    __nv_bfloat162 o[4];
#pragma unroll
    for (int j=0;j<4;j++){
        float a0 = acc[2*j],   r0 = a0 * fsigmoid(a0);
        float a1 = acc[2*j+1], r1 = a1 * fsigmoid(a1);
        o[j] = __floats2bfloat162_rn(r0, r1);
    }
    *(uint4*)(g_xc_bf + (size_t)l*DIN + c8) = *(uint4*)o;
}

#define GROWS 16
__global__ __launch_bounds__(256) void gates_kernel(
    const float* __restrict__ igw, const float* __restrict__ igb,
    const float* __restrict__ fgw, const float* __restrict__ fgb)
{
    extern __shared__ bf16 gbuf[];
    int l0 = blockIdx.x*GROWS, tid = threadIdx.x;
    const int CH = DIN/8;
    for (int i = tid; i < GROWS*3*CH; i += 256){
        int rr = i / (3*CH); int rem = i - rr*3*CH;
        int a = rem / CH;    int ch = rem - a*CH;
        const bf16* src = (a==0 ? g_q_bf : a==1 ? g_k_bf : g_v_bf) + (size_t)(l0+rr)*DIN + ch*8;
        *(uint4*)&gbuf[(size_t)rr*3*DIN + a*DIN + ch*8] = *(const uint4*)src;
    }
    __syncthreads();
    int w = tid >> 5, lane = tid & 31;
    const float* iw = igw + (size_t)w*3*DIN;
    const float* fw = fgw + (size_t)w*3*DIN;
    float si[GROWS] = {}, sf[GROWS] = {};
    for (int j = lane*8; j < 3*DIN; j += 256){
        float4 wi0 = *(const float4*)(iw + j), wi1 = *(const float4*)(iw + j + 4);
        float4 wf0 = *(const float4*)(fw + j), wf1 = *(const float4*)(fw + j + 4);
#pragma unroll
        for (int rr=0; rr<GROWS; rr++){
            uint4 u = *(uint4*)&gbuf[(size_t)rr*3*DIN + j];
            __nv_bfloat162* bp = (__nv_bfloat162*)&u;
            float2 g0 = __bfloat1622float2(bp[0]);
            float2 g1 = __bfloat1622float2(bp[1]);
            float2 g2 = __bfloat1622float2(bp[2]);
            float2 g3 = __bfloat1622float2(bp[3]);
            si[rr] = fmaf(g0.x, wi0.x, si[rr]); si[rr] = fmaf(g0.y, wi0.y, si[rr]);
            si[rr] = fmaf(g1.x, wi0.z, si[rr]); si[rr] = fmaf(g1.y, wi0.w, si[rr]);
            si[rr] = fmaf(g2.x, wi1.x, si[rr]); si[rr] = fmaf(g2.y, wi1.y, si[rr]);
            si[rr] = fmaf(g3.x, wi1.z, si[rr]); si[rr] = fmaf(g3.y, wi1.w, si[rr]);
            sf[rr] = fmaf(g0.x, wf0.x, sf[rr]); sf[rr] = fmaf(g0.y, wf0.y, sf[rr]);
            sf[rr] = fmaf(g1.x, wf0.z, sf[rr]); sf[rr] = fmaf(g1.y, wf0.w, sf[rr]);
            sf[rr] = fmaf(g2.x, wf1.x, sf[rr]); sf[rr] = fmaf(g2.y, wf1.y, sf[rr]);
            sf[rr] = fmaf(g3.x, wf1.z, sf[rr]); sf[rr] = fmaf(g3.y, wf1.w, sf[rr]);
        }
    }
#pragma unroll
    for (int off=16; off>0; off>>=1){
#pragma unroll
        for (int rr=0;rr<GROWS;rr++){
            si[rr] += __shfl_xor_sync(0xffffffffu, si[rr], off);
            sf[rr] += __shfl_xor_sync(0xffffffffu, sf[rr], off);
        }
    }
    if (lane == 0){
#pragma unroll
        for (int rr=0;rr<GROWS;rr++){
            g_ig[w*SEQ + l0+rr] = si[rr] + igb[w];
            g_fg[w*SEQ + l0+rr] = sf[rr] + fgb[w];
        }
    }
}

__global__ __launch_bounds__(256) void scan_kernel()
{
    __shared__ float lf[SEQ];
    __shared__ float tot[256];
    int h = blockIdx.x, tid = threadIdx.x;
    for (int m = tid; m < SEQ; m += 256){
        float f = g_fg[h*SEQ + m];
        lf[m] = fminf(f, 0.f) - log1pf(expf(-fabsf(f)));
    }
    __syncthreads();
    int base = tid * 8;
    float csl[8];
    float run = 0.f;
#pragma unroll
    for (int j=0;j<8;j++){ run += lf[base+j]; csl[j] = run; }
    tot[tid] = run; __syncthreads();
    for (int off=1; off<256; off<<=1){
        float v = (tid >= off) ? tot[tid-off] : 0.f;
        __syncthreads();
        tot[tid] += v;
        __syncthreads();
    }
    float excl = tot[tid] - run;
    float cs[8], cml[8];
    float rmax = -INFINITY;
#pragma unroll
    for (int j=0;j<8;j++){
        cs[j] = csl[j] + excl;
        float col = g_ig[h*SEQ + base + j] - cs[j];
        g_colt[h*SEQ + base + j] = col;
        rmax = fmaxf(rmax, col);
        cml[j] = rmax;
    }
    tot[tid] = rmax; __syncthreads();
    for (int off=1; off<256; off<<=1){
        float v = (tid >= off) ? tot[tid-off] : -INFINITY;
        __syncthreads();
        tot[tid] = fmaxf(tot[tid], v);
        __syncthreads();
    }
    float em = (tid > 0) ? tot[tid-1] : -INFINITY;
#pragma unroll
    for (int j=0;j<8;j++){
        float rm = fmaxf(em, cml[j]);
        g_rowt[h*SEQ + base + j] = -rm;
        g_expn[h*SEQ + base + j] = expf(-(cs[j] + rm));
    }
}

// group norm reading the two pav partial buffers
__global__ __launch_bounds__(256) void gn_kernel(const float* __restrict__ gnw,
    const float* __restrict__ gnb, const float* __restrict__ skip)
{
    int l = blockIdx.x, tid = threadIdx.x, w = tid >> 5, lane = tid & 31;
    int c0 = w*DHEAD + lane*8;
    float4 h0a = *(const float4*)(g_hfl  + (size_t)l*DIN + c0);
    float4 h1a = *(const float4*)(g_hfl  + (size_t)l*DIN + c0 + 4);
    float4 h0b = *(const float4*)(g_hfl2 + (size_t)l*DIN + c0);
    float4 h1b = *(const float4*)(g_hfl2 + (size_t)l*DIN + c0 + 4);
    float vals[8] = {h0a.x+h0b.x, h0a.y+h0b.y, h0a.z+h0b.z, h0a.w+h0b.w,
                     h1a.x+h1b.x, h1a.y+h1b.y, h1a.z+h1b.z, h1a.w+h1b.w};
    float s = 0.f, ss = 0.f;
#pragma unroll
    for (int j=0;j<8;j++){ s += vals[j]; ss += vals[j]*vals[j]; }
#pragma unroll
    for (int off=16; off>0; off>>=1){
        s  += __shfl_xor_sync(0xffffffffu, s,  off);
        ss += __shfl_xor_sync(0xffffffffu, ss, off);
    }
    float mean = s * (1.f/DHEAD);
    float var  = ss * (1.f/DHEAD) - mean*mean;
    float rstd = rsqrtf(var + 1e-5f);
    float4 gw0 = *(const float4*)(gnw + c0), gw1 = *(const float4*)(gnw + c0 + 4);
    float4 gb0 = *(const float4*)(gnb + c0), gb1 = *(const float4*)(gnb + c0 + 4);
    float4 sk0 = *(const float4*)(skip + c0), sk1 = *(const float4*)(skip + c0 + 4);
    uint4 uxc = *(const uint4*)(g_xc_bf + (size_t)l*DIN + c0);
    uint4 urs = *(const uint4*)(g_proj_bf + (size_t)l*(2*DIN) + DIN + c0);
    float gwv[8] = {gw0.x,gw0.y,gw0.z,gw0.w,gw1.x,gw1.y,gw1.z,gw1.w};
    float gbv[8] = {gb0.x,gb0.y,gb0.z,gb0.w,gb1.x,gb1.y,gb1.z,gb1.w};
    float skv[8] = {sk0.x,sk0.y,sk0.z,sk0.w,sk1.x,sk1.y,sk1.z,sk1.w};
    float xcv[8], rsv[8];
    {
        __nv_bfloat162* bx = (__nv_bfloat162*)&uxc;
        __nv_bfloat162* br = (__nv_bfloat162*)&urs;
#pragma unroll
        for (int j=0;j<4;j++){
            float2 fx = __bfloat1622float2(bx[j]); xcv[2*j]=fx.x; xcv[2*j+1]=fx.y;
            float2 fr = __bfloat1622float2(br[j]); rsv[2*j]=fr.x; rsv[2*j+1]=fr.y;
        }
    }
    __nv_bfloat162 o[4];
#pragma unroll
    for (int j=0;j<4;j++){
        float y0, y1;
        {
            float hn = (vals[2*j] - mean) * rstd;
            float h2 = hn*gwv[2*j] + gbv[2*j] + skv[2*j]*xcv[2*j];
            float r  = rsv[2*j];
            y0 = h2 * (r * fsigmoid(r));
        }
        {
            float hn = (vals[2*j+1] - mean) * rstd;
            float h2 = hn*gwv[2*j+1] + gbv[2*j+1] + skv[2*j+1]*xcv[2*j+1];
            float r  = rsv[2*j+1];
            y1 = h2 * (r * fsigmoid(r));
        }
        o[j] = __floats2bfloat162_rn(y0, y1);
    }
    *(uint4*)(g_yin_bf + (size_t)l*DIN + c0) = *(uint4*)o;
}

// ---------------- launch ----------------
extern "C" void kernel_launch(void* const* d_in, const int* in_sizes, int n_in,
                              void* d_out, int out_size)
{
    (void)in_sizes; (void)n_in; (void)out_size;
    const float* x    = (const float*)d_in[0];
    const float* ln1w = (const float*)d_in[2];
    const float* winw = (const float*)d_in[3];
    const float* winb = (const float*)d_in[4];
    const float* woutw= (const float*)d_in[5];
    const float* ck   = (const float*)d_in[6];
    const float* cb   = (const float*)d_in[7];
    const float* wq   = (const float*)d_in[8];
    const float* wk   = (const float*)d_in[9];
    const float* wv   = (const float*)d_in[10];
    const float* igw  = (const float*)d_in[11];
    const float* igb  = (const float*)d_in[12];
    const float* fgw  = (const float*)d_in[13];
    const float* fgb  = (const float*)d_in[14];
    const float* gnw  = (const float*)d_in[15];
    const float* gnb  = (const float*)d_in[16];
    const float* skip = (const float*)d_in[17];
    const float* ln2w = (const float*)d_in[18];
    const float* ffnw = (const float*)d_in[19];
    const float* ffnow= (const float*)d_in[20];
    float* out = (float*)d_out;

    static cudaStream_t s2;
    static cudaEvent_t evF, eWinw, eWt, eRest, eProj, eVt, eQK, eRes2, eF1a, eSkA;
    static int inited = 0;
    if (!inited){
        cudaStreamCreateWithFlags(&s2, cudaStreamNonBlocking);
        cudaEventCreateWithFlags(&evF,   cudaEventDisableTiming);
        cudaEventCreateWithFlags(&eWinw, cudaEventDisableTiming);
        cudaEventCreateWithFlags(&eWt,   cudaEventDisableTiming);
        cudaEventCreateWithFlags(&eRest, cudaEventDisableTiming);
        cudaEventCreateWithFlags(&eProj, cudaEventDisableTiming);
        cudaEventCreateWithFlags(&eVt,   cudaEventDisableTiming);
        cudaEventCreateWithFlags(&eQK,   cudaEventDisableTiming);
        cudaEventCreateWithFlags(&eRes2, cudaEventDisableTiming);
        cudaEventCreateWithFlags(&eF1a,  cudaEventDisableTiming);
        cudaEventCreateWithFlags(&eSkA,  cudaEventDisableTiming);
        cudaFuncSetAttribute(mma_nt_bf,    cudaFuncAttributeMaxDynamicSharedMemorySize, SMEM_GEMM);
        cudaFuncSetAttribute(mma_nt_sk,    cudaFuncAttributeMaxDynamicSharedMemorySize, SMEM_GEMM);
        cudaFuncSetAttribute(mma_ffn1,     cudaFuncAttributeMaxDynamicSharedMemorySize, SMEM_GEMM);
        cudaFuncSetAttribute(mma_qkv,      cudaFuncAttributeMaxDynamicSharedMemorySize, SMEM_GEMM);
        cudaFuncSetAttribute(mma_score_bf, cudaFuncAttributeMaxDynamicSharedMemorySize, SMEM_GEMM);
        cudaFuncSetAttribute(mma_pav_bf,   cudaFuncAttributeMaxDynamicSharedMemorySize, SMEM_GEMM);
        cudaFuncSetAttribute(gates_kernel, cudaFuncAttributeMaxDynamicSharedMemorySize, GROWS*3*DIN*2);
        inited = 1;
    }

    float *x2;
    bf16 *hln,*projb,*winwb,*yinb,*hfb,*g2b,*woutwb,*ffnowb;
    cudaGetSymbolAddress((void**)&x2,    g_x2);
    cudaGetSymbolAddress((void**)&hln,   g_hln_bf);
    cudaGetSymbolAddress((void**)&projb, g_proj_bf);
    cudaGetSymbolAddress((void**)&winwb, g_winw_bf);
    cudaGetSymbolAddress((void**)&yinb,  g_yin_bf);
    cudaGetSymbolAddress((void**)&hfb,   g_hf_bf);
    cudaGetSymbolAddress((void**)&g2b,   g_g2_bf);
    cudaGetSymbolAddress((void**)&woutwb, g_woutw_bf);
    cudaGetSymbolAddress((void**)&ffnowb, g_ffnow_bf);

    dim3 tb(32, 8);

    // ---- fork: weight prep on s2 ----
    cudaEventRecord(evF, 0);
    cudaStreamWaitEvent(s2, evF, 0);
    convert_winw<<<(CW_N0+255)/256, 256, 0, s2>>>(winw);
    cudaEventRecord(eWinw, s2);
    transpose_w_all<<<dim3(8,8,24), tb, 0, s2>>>(wq, wk, wv);
    cudaEventRecord(eWt, s2);
    convert_rest<<<(CW_N1+CW_N2+CW_N3+255)/256, 256, 0, s2>>>(woutw, ffnw, ffnow);
    cudaEventRecord(eRest, s2);

    // ---- main stream ----
    layernorm_bf<<<SEQ/8, 256>>>(x, ln1w, hln, DMOD);
    cudaStreamWaitEvent(0, eWinw, 0);
    // in-proj xi half (columns 0..2047) — critical path
    mma_nt_bf<<<dim3(DIN/BN, SEQ/BM), 256, SMEM_GEMM>>>(hln, winwb, winb, 0,
        (float*)0, projb, DMOD, DMOD, DMOD, 0, 0, 2*DIN);
    cudaEventRecord(eProj, 0);

    // s2: V GEMM + V transpose
    cudaStreamWaitEvent(s2, eProj, 0);
    mma_qkv<<<dim3(2, SEQ/BM, NHEAD), 256, SMEM_GEMM, s2>>>(2*NHEAD);   // v
    transpose_v_bf<<<dim3(SEQ/32, DHEAD/32, NHEAD), tb, 0, s2>>>();
    cudaEventRecord(eVt, s2);

    // main: conv, then q/k
    conv_silu_kernel<<<SEQ, 256>>>(ck, cb);
    cudaStreamWaitEvent(0, eWt, 0);
    mma_qkv<<<dim3(2, SEQ/BM, 2*NHEAD), 256, SMEM_GEMM>>>(0);           // q,k
    cudaEventRecord(eQK, 0);

    // s2: in-proj res half — fills the gates/scan bubble
    cudaStreamWaitEvent(s2, eQK, 0);
    mma_nt_bf<<<dim3(DIN/BN, SEQ/BM), 256, SMEM_GEMM, s2>>>(hln,
        winwb + (size_t)DIN*DMOD, winb + DIN, 0,
        (float*)0, projb + DIN, DMOD, DMOD, DMOD, 0, 0, 2*DIN);
    cudaEventRecord(eRes2, s2);

    // main: gates/scan
    cudaStreamWaitEvent(0, eVt, 0);
    gates_kernel<<<SEQ/GROWS, 256, GROWS*3*DIN*2>>>(igw, igb, fgw, fgb);
    scan_kernel<<<NHEAD, 256>>>();
    mma_score_bf<<<dim3(SEQ/BN, SEQ/BM, NHEAD), 256, SMEM_GEMM>>>();
    mma_pav_bf<<<dim3(2, SEQ/BM, 2*NHEAD), 256, SMEM_GEMM>>>();
    cudaStreamWaitEvent(0, eRes2, 0);
    gn_kernel<<<SEQ, 256>>>(gnw, gnb, skip);
    cudaStreamWaitEvent(0, eRest, 0);
    mma_nt_sk<<<dim3(DMOD/BN, SEQ/BM, 2), 256, SMEM_GEMM>>>(yinb, woutwb, DIN/2, DIN, DIN, 0);
    ln_combine<<<SEQ/8, 256>>>(x, ln2w, hfb, x2);

    // ffn pipeline: half-A -> (s2: ffnout K-half0) || (main: half-B) -> main: ffnout K-half1
    mma_ffn1<<<dim3(16, SEQ/BM), 256, SMEM_GEMM>>>(0);        // N cols 0..2047 -> t 0..1023
    cudaEventRecord(eF1a, 0);
    cudaStreamWaitEvent(s2, eF1a, 0);
    mma_nt_sk<<<dim3(DMOD/BN, SEQ/BM, 1), 256, SMEM_GEMM, s2>>>(g2b, ffnowb, DHID/2, DHID, DHID, 0);
    cudaEventRecord(eSkA, s2);
    mma_ffn1<<<dim3(16, SEQ/BM), 256, SMEM_GEMM>>>(16);       // N cols 2048..4095 -> t 1024..2047
    mma_nt_sk<<<dim3(DMOD/BN, SEQ/BM, 1), 256, SMEM_GEMM>>>(g2b, ffnowb, DHID/2, DHID, DHID, 1);
    cudaStreamWaitEvent(0, eSkA, 0);
    final_combine<<<SEQ*DMOD/4/256, 256>>>(out);
}

// round 16
// speedup vs baseline: 1.0281x; 1.0281x over previous
#include <cuda_runtime.h>
#include <cuda_bf16.h>
#include <math.h>

#define SEQ   2048
#define DMOD  1024
#define DIN   2048
#define NHEAD 8
#define DHEAD 256
#define DHID  2048

typedef __nv_bfloat16 bf16;

// ---------------- scratch (allocation-free: __device__ globals) ----------------
__device__ float g_ig  [NHEAD*SEQ];
__device__ float g_fg  [NHEAD*SEQ];
__device__ float g_rowt[NHEAD*SEQ];
__device__ float g_colt[NHEAD*SEQ];
__device__ float g_expn[NHEAD*SEQ];
__device__ float g_psum[NHEAD*16*SEQ];
__device__ float g_hfl [SEQ*DIN];
__device__ float g_hfl2[SEQ*DIN];
__device__ float g_x2  [SEQ*DMOD];
__device__ float g_sk0 [SEQ*DMOD];
__device__ float g_sk1 [SEQ*DMOD];

__device__ bf16 g_hln_bf [SEQ*DMOD];
__device__ bf16 g_proj_bf[SEQ*2*DIN];
__device__ bf16 g_xc_bf  [SEQ*DIN];
__device__ bf16 g_q_bf   [SEQ*DIN];
__device__ bf16 g_k_bf   [SEQ*DIN];
__device__ bf16 g_v_bf   [SEQ*DIN];
__device__ bf16 g_vt_bf  [(size_t)NHEAD*DHEAD*SEQ];
__device__ bf16 g_C_bf   [(size_t)NHEAD*SEQ*SEQ];
__device__ bf16 g_yin_bf [SEQ*DIN];
__device__ bf16 g_hf_bf  [SEQ*DMOD];
__device__ bf16 g_g2_bf  [SEQ*DHID];
__device__ bf16 g_winw_bf[2*DIN*DMOD];
__device__ bf16 g_woutw_bf[DMOD*DIN];
__device__ bf16 g_ffnw_bf[2*DHID*DMOD];   // ROW-REORDERED: row 2t = a-row t, row 2t+1 = z-row DHID+t
__device__ bf16 g_ffnow_bf[DMOD*DHID];
__device__ bf16 g_wqt_bf[NHEAD*DHEAD*DHEAD];
__device__ bf16 g_wkt_bf[NHEAD*DHEAD*DHEAD];
__device__ bf16 g_wvt_bf[NHEAD*DHEAD*DHEAD];

// ---------------- tile config ----------------
#define BM 128
#define BN 128
#define BKB 64                   // bf16 elements per stage (128B rows)
#define TILEB 16384              // 128 rows x 128B
#define SMEM_GEMM (6*TILEB)      // triple-buffered A+B = 96KB

__device__ __forceinline__ unsigned sw128(unsigned o){ return o ^ ((o>>3)&0x70); }

__device__ __forceinline__ void cp16(void* smem_dst, const void* gsrc){
    unsigned s = (unsigned)__cvta_generic_to_shared(smem_dst);
    asm volatile("cp.async.cg.shared.global [%0], [%1], 16;" :: "r"(s), "l"(gsrc));
}
#define CP_COMMIT() asm volatile("cp.async.commit_group;")
#define CP_WAIT(n)  asm volatile("cp.async.wait_group %0;" :: "n"(n))

__device__ __forceinline__ void ldsm4(unsigned r[4], const void* p){
    unsigned a = (unsigned)__cvta_generic_to_shared(p);
    asm volatile("ldmatrix.sync.aligned.m8n8.x4.shared.b16 {%0,%1,%2,%3}, [%4];"
        : "=r"(r[0]),"=r"(r[1]),"=r"(r[2]),"=r"(r[3]) : "r"(a));
}

#define MMA_BF16(d, a, b) \
  asm volatile("mma.sync.aligned.m16n8k16.row.col.f32.bf16.bf16.f32 " \
    "{%0,%1,%2,%3},{%4,%5,%6,%7},{%8,%9},{%0,%1,%2,%3};" \
    : "+f"((d)[0]),"+f"((d)[1]),"+f"((d)[2]),"+f"((d)[3]) \
    : "r"((a)[0]),"r"((a)[1]),"r"((a)[2]),"r"((a)[3]),"r"((b)[0]),"r"((b)[1]))

__device__ __forceinline__ float ftanh(float x){
    float y; asm("tanh.approx.f32 %0, %1;" : "=f"(y) : "f"(x)); return y;
}
__device__ __forceinline__ float fsigmoid(float x){ return 1.f / (1.f + __expf(-x)); }
__device__ __forceinline__ float fgelu(float a){
    float t = ftanh(0.7978845608028654f * (a + 0.044715f*a*a*a));
    return 0.5f * a * (1.f + t);
}

__device__ __forceinline__ void stage_bf(const bf16* __restrict__ src, int ld,
      int row0, int k0, char* S, int tid)
{
#pragma unroll
    for (int it=0; it<4; it++){
        int idx = it*256 + tid;
        int r = idx>>3, ch = idx&7;
        cp16(S + sw128(r*128 + ch*16), src + (size_t)(row0+r)*ld + k0 + ch*8);
    }
}

__device__ __forceinline__ void compute_bf(const char* __restrict__ As,
    const char* __restrict__ Bs, float acc[4][4][4], int lane, int wm, int wn)
{
    const int l15 = lane&15, lh = lane>>4, l7 = lane&7, lb3 = (lane>>3)&1;
#pragma unroll
    for (int kk=0;kk<4;kk++){
        unsigned a[4][4];
#pragma unroll
        for (int mt=0;mt<4;mt++)
            ldsm4(a[mt], As + sw128((wm + mt*16 + l15)*128 + (kk*2 + lh)*16));
        unsigned b[2][4];
#pragma unroll
        for (int bp=0;bp<2;bp++){
            unsigned row = wn + bp*16 + lh*8 + l7;
            ldsm4(b[bp], Bs + sw128(row*128 + (kk*2 + lb3)*16));
        }
#pragma unroll
        for (int mt=0;mt<4;mt++)
#pragma unroll
            for (int nt=0;nt<4;nt++)
                MMA_BF16(acc[mt][nt], a[mt], b[nt>>1] + (nt&1)*2);
    }
}

// 3-stage cp.async pipeline, one barrier per K-step
__device__ __forceinline__ void gemm_loop_bf(const bf16* __restrict__ A, int lda,
    const bf16* __restrict__ B, int ldb, int m0, int n0, int K,
    char* smem, float acc[4][4][4], int tid, int lane, int wm, int wn)
{
    const int nsteps = K >> 6;
    stage_bf(A, lda, m0, 0, smem, tid);
    stage_bf(B, ldb, n0, 0, smem + TILEB, tid);
    CP_COMMIT();
    if (nsteps > 1){
        stage_bf(A, lda, m0, BKB, smem + 2*TILEB, tid);
        stage_bf(B, ldb, n0, BKB, smem + 3*TILEB, tid);
        CP_COMMIT();
    }
    for (int s=0; s<nsteps; s++){
        if (s+1 < nsteps) { CP_WAIT(1); } else { CP_WAIT(0); }
        __syncthreads();
        if (s+2 < nsteps){
            char* T = smem + ((s+2)%3)*2*TILEB;
            stage_bf(A, lda, m0, (s+2)*BKB, T, tid);
            stage_bf(B, ldb, n0, (s+2)*BKB, T + TILEB, tid);
            CP_COMMIT();
        }
        char* Cur = smem + (s%3)*2*TILEB;
        compute_bf(Cur, Cur + TILEB, acc, lane, wm, wn);
    }
    __syncthreads();   // smem safe for reuse after loop
}

// ---------------- GEMM kernels ----------------

// C[m,n] = sum_k A[m,k]*B[n,k] (+bias) (+resid); optional fp32 out, optional bf16 out
__global__ __launch_bounds__(256, 2) void mma_nt_bf(
    const bf16* __restrict__ A, const bf16* __restrict__ B,
    const float* __restrict__ bias, const float* __restrict__ resid,
    float* __restrict__ Cf, bf16* __restrict__ Cb,
    int K, int lda, int ldb, int ldc, int ldr, int ldcb)
{
    extern __shared__ char smem[];
    const int tid=threadIdx.x, lane=tid&31, wid=tid>>5;
    const int wm=(wid>>2)*64, wn=(wid&3)*32;
    const int m0=blockIdx.y*BM, n0=blockIdx.x*BN;
    float acc[4][4][4] = {};
    gemm_loop_bf(A, lda, B, ldb, m0, n0, K, smem, acc, tid, lane, wm, wn);
    const int gr=lane>>2, gc=lane&3;
#pragma unroll
    for (int mt=0;mt<4;mt++){
#pragma unroll
        for (int nt=0;nt<4;nt++){
            int row = m0+wm+mt*16+gr;
            int col = n0+wn+nt*8+gc*2;
            float b0=0.f,b1=0.f;
            if (bias){ b0=bias[col]; b1=bias[col+1]; }
            float r00=0,r01=0,r10=0,r11=0;
            if (resid){
                const float* rp  = resid + (size_t)row*ldr + col;
                const float* rp2 = resid + (size_t)(row+8)*ldr + col;
                r00=rp[0]; r01=rp[1]; r10=rp2[0]; r11=rp2[1];
            }
            float v00=acc[mt][nt][0]+b0+r00, v01=acc[mt][nt][1]+b1+r01;
            float v10=acc[mt][nt][2]+b0+r10, v11=acc[mt][nt][3]+b1+r11;
            if (Cf){
                *(float2*)(Cf + (size_t)row*ldc + col)     = make_float2(v00,v01);
                *(float2*)(Cf + (size_t)(row+8)*ldc + col) = make_float2(v10,v11);
            }
            if (Cb){
                *(__nv_bfloat162*)(Cb + (size_t)row*ldcb + col)     = __floats2bfloat162_rn(v00,v01);
                *(__nv_bfloat162*)(Cb + (size_t)(row+8)*ldcb + col) = __floats2bfloat162_rn(v10,v11);
            }
        }
    }
}

// split-K NT GEMM: kidx = blockIdx.z + kbase selects K-half and output buffer
__global__ __launch_bounds__(256, 2) void mma_nt_sk(
    const bf16* __restrict__ A, const bf16* __restrict__ B,
    int Khalf, int lda, int ldb, int kbase)
{
    extern __shared__ char smem[];
    const int tid=threadIdx.x, lane=tid&31, wid=tid>>5;
    const int wm=(wid>>2)*64, wn=(wid&3)*32;
    const int m0=blockIdx.y*BM, n0=blockIdx.x*BN;
    const int kidx = blockIdx.z + kbase;
    const int koff = kidx * Khalf;
    float* P = kidx ? g_sk1 : g_sk0;
    float acc[4][4][4] = {};
    gemm_loop_bf(A + koff, lda, B + koff, ldb, m0, n0, Khalf, smem, acc, tid, lane, wm, wn);
    const int gr=lane>>2, gc=lane&3;
#pragma unroll
    for (int mt=0;mt<4;mt++){
#pragma unroll
        for (int nt=0;nt<4;nt++){
            int row = m0+wm+mt*16+gr;
            int col = n0+wn+nt*8+gc*2;
            *(float2*)(P + (size_t)row*DMOD + col)     = make_float2(acc[mt][nt][0],acc[mt][nt][1]);
            *(float2*)(P + (size_t)(row+8)*DMOD + col) = make_float2(acc[mt][nt][2],acc[mt][nt][3]);
        }
    }
}

// ffn-in GEMM with fused GELU-pair epilogue (interleaved weights).
__global__ __launch_bounds__(256, 2) void mma_ffn1()
{
    extern __shared__ char smem[];
    const int tid=threadIdx.x, lane=tid&31, wid=tid>>5;
    const int wm=(wid>>2)*64, wn=(wid&3)*32;
    const int m0=blockIdx.y*BM, n0=blockIdx.x*BN;
    float acc[4][4][4] = {};
    gemm_loop_bf(g_hf_bf, DMOD, g_ffnw_bf, DMOD, m0, n0, DMOD, smem, acc, tid, lane, wm, wn);
    const int gr=lane>>2, gc=lane&3;
#pragma unroll
    for (int mt=0;mt<4;mt++){
#pragma unroll
        for (int nt=0;nt<4;nt++){
            int row = m0+wm+mt*16+gr;
            int col = n0+wn+nt*8+gc*2;   // even: a, odd: z
            int t = col >> 1;
            g_g2_bf[(size_t)row*DHID + t]     = __float2bfloat16_rn(fgelu(acc[mt][nt][0]) * acc[mt][nt][1]);
            g_g2_bf[(size_t)(row+8)*DHID + t] = __float2bfloat16_rn(fgelu(acc[mt][nt][2]) * acc[mt][nt][3]);
        }
    }
}

// fused q/k/v with z-base: z = blockIdx.z + zbase; which = z>>3 (0=q,1=k,2=v)
__global__ __launch_bounds__(256, 2) void mma_qkv(int zbase)
{
    const int z = blockIdx.z + zbase;
    const int which = z >> 3;
    const int h = z & 7;
    const bf16* A; int lda; const bf16* B; bf16* C;
    if (which == 0){ A = g_xc_bf   + h*DHEAD; lda = DIN;   B = g_wqt_bf + h*DHEAD*DHEAD; C = g_q_bf + h*DHEAD; }
    else if (which == 1){ A = g_xc_bf + h*DHEAD; lda = DIN; B = g_wkt_bf + h*DHEAD*DHEAD; C = g_k_bf + h*DHEAD; }
    else { A = g_proj_bf + h*DHEAD; lda = 2*DIN; B = g_wvt_bf + h*DHEAD*DHEAD; C = g_v_bf + h*DHEAD; }
    extern __shared__ char smem[];
    const int tid=threadIdx.x, lane=tid&31, wid=tid>>5;
    const int wm=(wid>>2)*64, wn=(wid&3)*32;
    const int m0=blockIdx.y*BM, n0=blockIdx.x*BN;
    float acc[4][4][4] = {};
    gemm_loop_bf(A, lda, B, DHEAD, m0, n0, DHEAD, smem, acc, tid, lane, wm, wn);
    const int gr=lane>>2, gc=lane&3;
#pragma unroll
    for (int mt=0;mt<4;mt++){
#pragma unroll
        for (int nt=0;nt<4;nt++){
            int row = m0+wm+mt*16+gr;
            int col = n0+wn+nt*8+gc*2;
            *(__nv_bfloat162*)(C + (size_t)row*DIN + col)     = __floats2bfloat162_rn(acc[mt][nt][0],acc[mt][nt][1]);
            *(__nv_bfloat162*)(C + (size_t)(row+8)*DIN + col) = __floats2bfloat162_rn(acc[mt][nt][2],acc[mt][nt][3]);
        }
    }
}

// scores: C[h][l,m] = (q·k)/16 * exp(rowt[l]+colt[m]) masked; bf16 out + fp32 tile row-sums.
// Decay factorized per tile: exp(rl+cm) = exp(rl+cref)*exp(cm-cref), cref = colt[m0]
// -> 256 exps per CTA instead of 16384 (MUFU was the epilogue bottleneck).
__global__ __launch_bounds__(256, 2) void mma_score_bf()
{
    const int h  = blockIdx.z;
    const int l0 = blockIdx.y * BM;
    const int m0 = blockIdx.x * BN;
    if (m0 >= l0 + BM) return;   // fully-masked tile: skipped (never read downstream)
    extern __shared__ char smem[];
    const bf16* A = g_q_bf + h*DHEAD;
    const bf16* B = g_k_bf + h*DHEAD;
    const int tid=threadIdx.x, lane=tid&31, wid=tid>>5;
    const int wm=(wid>>2)*64, wn=(wid&3)*32;
    float acc[4][4][4] = {};
    gemm_loop_bf(A, DIN, B, DIN, l0, m0, DHEAD, smem, acc, tid, lane, wm, wn);

    float* sred   = (float*)smem;        // 512 floats
    float* erow_s = sred + 512;          // 128 floats
    float* ecol_s = erow_s + 128;        // 128 floats
    const float* rt = g_rowt + h*SEQ;
    const float* ct = g_colt + h*SEQ;
    const float cref = ct[m0];
    if (tid < 128){
        erow_s[tid] = __expf(rt[l0 + tid] + cref);
    } else {
        int j = tid - 128;
        ecol_s[j] = __expf(ct[m0 + j] - cref);
    }
    __syncthreads();

    bf16* Cb = g_C_bf + (size_t)h*SEQ*SEQ;
    const int gr=lane>>2, gc=lane&3;
#pragma unroll
    for (int mt=0;mt<4;mt++){
        int lr = wm+mt*16+gr;
        int l = l0+lr;
        float rl0 = erow_s[lr]   * 0.0625f;
        float rl1 = erow_s[lr+8] * 0.0625f;
        float rs0 = 0.f, rs1 = 0.f;
#pragma unroll
        for (int nt=0;nt<4;nt++){
            int mc = wn+nt*8+gc*2;
            int m = m0+mc;
            float cm0 = ecol_s[mc], cm1 = ecol_s[mc+1];
            float v00 = (m   <= l  ) ? acc[mt][nt][0]*rl0*cm0 : 0.f;
            float v01 = (m+1 <= l  ) ? acc[mt][nt][1]*rl0*cm1 : 0.f;
            float v10 = (m   <= l+8) ? acc[mt][nt][2]*rl1*cm0 : 0.f;
            float v11 = (m+1 <= l+8) ? acc[mt][nt][3]*rl1*cm1 : 0.f;
            rs0 += v00 + v01;
            rs1 += v10 + v11;
            *(__nv_bfloat162*)(Cb + (size_t)l*SEQ + m)     = __floats2bfloat162_rn(v00,v01);
            *(__nv_bfloat162*)(Cb + (size_t)(l+8)*SEQ + m) = __floats2bfloat162_rn(v10,v11);
        }
        rs0 += __shfl_xor_sync(0xffffffffu, rs0, 1);
        rs0 += __shfl_xor_sync(0xffffffffu, rs0, 2);
        rs1 += __shfl_xor_sync(0xffffffffu, rs1, 1);
        rs1 += __shfl_xor_sync(0xffffffffu, rs1, 2);
        if (gc == 0){
            sred[(wm+mt*16+gr)*4   + (wid&3)] = rs0;
            sred[(wm+mt*16+gr+8)*4 + (wid&3)] = rs1;
        }
    }
    __syncthreads();
    if (tid < 128){
        float s = sred[tid*4] + sred[tid*4+1] + sred[tid*4+2] + sred[tid*4+3];
        g_psum[((size_t)h*16 + blockIdx.x)*SEQ + l0 + tid] = s;
    }
}

// hflat partials (split-K over the causal range): grid.z = sp*NHEAD + h
__global__ __launch_bounds__(256, 2) void mma_pav_bf()
{
    const int z  = blockIdx.z;
    const int sp = z >> 3;
    const int h  = z & 7;
    const int l0 = blockIdx.y * BM;
    const int n0 = blockIdx.x * BN;
    extern __shared__ char smem[];
    __shared__ float inrm_s[BM];
    const int tid=threadIdx.x, lane=tid&31, wid=tid>>5;
    if (tid < BM){
        int l = l0 + tid;
        int ntl = (l >> 7) + 1;
        float s = 0.f;
        for (int t=0; t<ntl; t++) s += g_psum[((size_t)h*16 + t)*SEQ + l];
        float n = fmaxf(fabsf(s), g_expn[h*SEQ + l]) + 1e-6f;
        inrm_s[tid] = 1.0f / n;
    }
    const int Kmax  = l0 + BM;
    const int Khalf = Kmax >> 1;
    const int k0 = sp ? Khalf : 0;
    const int Klen = sp ? (Kmax - Khalf) : Khalf;
    const bf16* A = g_C_bf + (size_t)h*SEQ*SEQ + k0;
    const bf16* B = g_vt_bf + (size_t)h*DHEAD*SEQ + k0;
    float* OUT = sp ? g_hfl2 : g_hfl;
    const int wm=(wid>>2)*64, wn=(wid&3)*32;
    float acc[4][4][4] = {};
    gemm_loop_bf(A, SEQ, B, SEQ, l0, n0, Klen, smem, acc, tid, lane, wm, wn);
    const int gr=lane>>2, gc=lane&3;
#pragma unroll
    for (int mt=0;mt<4;mt++){
#pragma unroll
        for (int nt=0;nt<4;nt++){
            int lr = wm+mt*16+gr;
            int l = l0+lr;
            int col = n0+wn+nt*8+gc*2;
            float s0 = inrm_s[lr];
            float s1 = inrm_s[lr+8];
            float* c0 = OUT + (size_t)l*DIN + h*DHEAD + col;
            float* c1 = OUT + (size_t)(l+8)*DIN + h*DHEAD + col;
            *(float2*)c0 = make_float2(acc[mt][nt][0]*s0, acc[mt][nt][1]*s0);
            *(float2*)c1 = make_float2(acc[mt][nt][2]*s1, acc[mt][nt][3]*s1);
        }
    }
}

// ---------------- weight prep ----------------
#define CW_N0 524288
#define CW_N1 262144
#define CW_N2 262144
#define CW_N3 524288
__device__ __forceinline__ void cvt8(const float* s, bf16* d){
    float4 a = ((const float4*)s)[0], b = ((const float4*)s)[1];
    __nv_bfloat162 o[4] = { __floats2bfloat162_rn(a.x,a.y), __floats2bfloat162_rn(a.z,a.w),
                            __floats2bfloat162_rn(b.x,b.y), __floats2bfloat162_rn(b.z,b.w) };
    *(uint4*)d = *(uint4*)o;
}
__global__ void convert_winw(const float* __restrict__ winw)
{
    int i = blockIdx.x*256 + threadIdx.x;
    if (i < CW_N0) cvt8(winw + (size_t)i*8, g_winw_bf + (size_t)i*8);
}
__global__ void convert_rest(const float* __restrict__ woutw,
                             const float* __restrict__ ffnw, const float* __restrict__ ffnow)
{
    int i = blockIdx.x*256 + threadIdx.x;
    if (i < CW_N1){
        cvt8(woutw + (size_t)i*8, g_woutw_bf + (size_t)i*8);
    } else if (i < CW_N1+CW_N2){
        int j = i - CW_N1;
        cvt8(ffnow + (size_t)j*8, g_ffnow_bf + (size_t)j*8);
    } else {
        int j = i - CW_N1 - CW_N2;
        if (j < CW_N3){
            int r = j >> 7, c8 = (j & 127) * 8;
            int src = (r & 1) ? (DHID + (r>>1)) : (r>>1);
            cvt8(ffnw + (size_t)src*DMOD + c8, g_ffnw_bf + (size_t)r*DMOD + c8);
        }
    }
}

__global__ void transpose_w_all(const float* __restrict__ wq, const float* __restrict__ wk,
                                const float* __restrict__ wv)
{
    __shared__ float t[32][33];
    int z = blockIdx.z;
    int which = z >> 3, h = z & 7;
    const float* I = (which==0 ? wq : which==1 ? wk : wv) + (size_t)h*DHEAD*DHEAD;
    bf16* O = (which==0 ? g_wqt_bf : which==1 ? g_wkt_bf : g_wvt_bf) + (size_t)h*DHEAD*DHEAD;
    int k0 = blockIdx.y*32, d0 = blockIdx.x*32;
    int x = threadIdx.x, y = threadIdx.y;
#pragma unroll
    for (int i=0;i<32;i+=8) t[y+i][x] = I[(size_t)(k0+y+i)*DHEAD + d0 + x];
    __syncthreads();
#pragma unroll
    for (int i=0;i<32;i+=8) O[(size_t)(d0+y+i)*DHEAD + k0 + x] = __float2bfloat16_rn(t[x][y+i]);
}

__global__ void transpose_v_bf()
{
    __shared__ float t[32][33];
    int h = blockIdx.z;
    int m0 = blockIdx.x*32, d0 = blockIdx.y*32;
    int x = threadIdx.x, y = threadIdx.y;
#pragma unroll
    for (int i=0;i<32;i+=8) t[y+i][x] = __bfloat162float(g_v_bf[(size_t)(m0+y+i)*DIN + h*DHEAD + d0 + x]);
    __syncthreads();
#pragma unroll
    for (int i=0;i<32;i+=8)
        g_vt_bf[((size_t)h*DHEAD + d0+y+i)*SEQ + m0 + x] = __float2bfloat16_rn(t[x][y+i]);
}

// ---------------- elementwise / reduction kernels ----------------
__global__ __launch_bounds__(256) void layernorm_bf(const float* __restrict__ x,
    const float* __restrict__ w, bf16* __restrict__ out, int cols)
{
    int wrp = threadIdx.x >> 5, lane = threadIdx.x & 31;
    int row = blockIdx.x*8 + wrp;
    const float* xr = x + (size_t)row*cols;
    float4 v[8];
    float s = 0.f, ss = 0.f;
#pragma unroll
    for (int i=0;i<8;i++){
        v[i] = ((const float4*)xr)[lane + i*32];
        s  += v[i].x + v[i].y + v[i].z + v[i].w;
        ss += v[i].x*v[i].x + v[i].y*v[i].y + v[i].z*v[i].z + v[i].w*v[i].w;
    }
#pragma unroll
    for (int off=16; off>0; off>>=1){
        s  += __shfl_xor_sync(0xffffffffu, s,  off);
        ss += __shfl_xor_sync(0xffffffffu, ss, off);
    }
    float mean = s / cols;
    float var  = ss / cols - mean*mean;
    float rstd = rsqrtf(var + 1e-5f);
    bf16* orow = out + (size_t)row*cols;
#pragma unroll
    for (int i=0;i<8;i++){
        float4 wv = ((const float4*)w)[lane + i*32];
        __nv_bfloat162 o0 = __floats2bfloat162_rn((v[i].x-mean)*rstd*wv.x, (v[i].y-mean)*rstd*wv.y);
        __nv_bfloat162 o1 = __floats2bfloat162_rn((v[i].z-mean)*rstd*wv.z, (v[i].w-mean)*rstd*wv.w);
        uint2 pk = make_uint2(*(unsigned*)&o0, *(unsigned*)&o1);
        *(uint2*)(orow + (lane + i*32)*4) = pk;
    }
}

// x2 = x + P0 + P1; hf = LN(x2)*w (split-K combine + LN fused)
__global__ __launch_bounds__(256) void ln_combine(const float* __restrict__ x,
    const float* __restrict__ w, bf16* __restrict__ out, float* __restrict__ x2)
{
    const int cols = DMOD;
    int wrp = threadIdx.x >> 5, lane = threadIdx.x & 31;
    int row = blockIdx.x*8 + wrp;
    const float* xr = x + (size_t)row*cols;
    const float* p0 = g_sk0 + (size_t)row*cols;
    const float* p1 = g_sk1 + (size_t)row*cols;
    float4 v[8];
    float s = 0.f, ss = 0.f;
#pragma unroll
    for (int i=0;i<8;i++){
        float4 a = ((const float4*)xr)[lane + i*32];
        float4 b = ((const float4*)p0)[lane + i*32];
        float4 c = ((const float4*)p1)[lane + i*32];
        v[i] = make_float4(a.x+b.x+c.x, a.y+b.y+c.y, a.z+b.z+c.z, a.w+b.w+c.w);
        s  += v[i].x + v[i].y + v[i].z + v[i].w;
        ss += v[i].x*v[i].x + v[i].y*v[i].y + v[i].z*v[i].z + v[i].w*v[i].w;
    }
#pragma unroll
    for (int off=16; off>0; off>>=1){
        s  += __shfl_xor_sync(0xffffffffu, s,  off);
        ss += __shfl_xor_sync(0xffffffffu, ss, off);
    }
    float mean = s / cols;
    float var  = ss / cols - mean*mean;
    float rstd = rsqrtf(var + 1e-5f);
    bf16* orow = out + (size_t)row*cols;
    float* x2r = x2 + (size_t)row*cols;
#pragma unroll
    for (int i=0;i<8;i++){
        ((float4*)x2r)[lane + i*32] = v[i];
        float4 wv = ((const float4*)w)[lane + i*32];
        __nv_bfloat162 o0 = __floats2bfloat162_rn((v[i].x-mean)*rstd*wv.x, (v[i].y-mean)*rstd*wv.y);
        __nv_bfloat162 o1 = __floats2bfloat162_rn((v[i].z-mean)*rstd*wv.z, (v[i].w-mean)*rstd*wv.w);
        uint2 pk = make_uint2(*(unsigned*)&o0, *(unsigned*)&o1);
        *(uint2*)(orow + (lane + i*32)*4) = pk;
    }
}

__global__ void final_combine(float* __restrict__ out)
{
    int i = blockIdx.x*256 + threadIdx.x;
    if (i >= SEQ*DMOD/4) return;
    float4 a = ((const float4*)g_x2)[i];
    float4 b = ((const float4*)g_sk0)[i];
    float4 c = ((const float4*)g_sk1)[i];
    ((float4*)out)[i] = make_float4(a.x+b.x+c.x, a.y+b.y+c.y, a.z+b.z+c.z, a.w+b.w+c.w);
}

__global__ __launch_bounds__(256) void conv_silu_kernel(const float* __restrict__ ck, const float* __restrict__ cb)
{
    int l = blockIdx.x;
    int c8 = threadIdx.x * 8;
    float acc[8];
    {
        float4 b0 = *(const float4*)(cb + c8);
        float4 b1 = *(const float4*)(cb + c8 + 4);
        acc[0]=b0.x; acc[1]=b0.y; acc[2]=b0.z; acc[3]=b0.w;
        acc[4]=b1.x; acc[5]=b1.y; acc[6]=b1.z; acc[7]=b1.w;
    }
    float4 kt[8];
#pragma unroll
    for (int j=0;j<8;j++) kt[j] = *(const float4*)(ck + (c8+j)*4);
#pragma unroll
    for (int t=0;t<4;t++){
        int ls = l - t;
        if (ls < 0) break;
        uint4 u = *(const uint4*)(g_proj_bf + (size_t)ls*(2*DIN) + c8);
        __nv_bfloat162* bp = (__nv_bfloat162*)&u;
        float tap[8];
#pragma unroll
        for (int j=0;j<4;j++){ float2 f = __bfloat1622float2(bp[j]); tap[2*j]=f.x; tap[2*j+1]=f.y; }
#pragma unroll
        for (int j=0;j<8;j++)
            acc[j] = fmaf(tap[j], ((float*)&kt[j])[t], acc[j]);
    }
    __nv_bfloat162 o[4];
#pragma unroll
    for (int j=0;j<4;j++){
        float a0 = acc[2*j],   r0 = a0 * fsigmoid(a0);
        float a1 = acc[2*j+1], r1 = a1 * fsigmoid(a1);
        o[j] = __floats2bfloat162_rn(r0, r1);
    }
    *(uint4*)(g_xc_bf + (size_t)l*DIN + c8) = *(uint4*)o;
}

#define GROWS 16
__global__ __launch_bounds__(256) void gates_kernel(
    const float* __restrict__ igw, const float* __restrict__ igb,
    const float* __restrict__ fgw, const float* __restrict__ fgb)
{
    extern __shared__ bf16 gbuf[];
    int l0 = blockIdx.x*GROWS, tid = threadIdx.x;
    const int CH = DIN/8;
    for (int i = tid; i < GROWS*3*CH; i += 256){
        int rr = i / (3*CH); int rem = i - rr*3*CH;
        int a = rem / CH;    int ch = rem - a*CH;
        const bf16* src = (a==0 ? g_q_bf : a==1 ? g_k_bf : g_v_bf) + (size_t)(l0+rr)*DIN + ch*8;
        *(uint4*)&gbuf[(size_t)rr*3*DIN + a*DIN + ch*8] = *(const uint4*)src;
    }
    __syncthreads();
    int w = tid >> 5, lane = tid & 31;
    const float* iw = igw + (size_t)w*3*DIN;
    const float* fw = fgw + (size_t)w*3*DIN;
    float si[GROWS] = {}, sf[GROWS] = {};
    for (int j = lane*8; j < 3*DIN; j += 256){
        float4 wi0 = *(const float4*)(iw + j), wi1 = *(const float4*)(iw + j + 4);
        float4 wf0 = *(const float4*)(fw + j), wf1 = *(const float4*)(fw + j + 4);
#pragma unroll
        for (int rr=0; rr<GROWS; rr++){
            uint4 u = *(uint4*)&gbuf[(size_t)rr*3*DIN + j];
            __nv_bfloat162* bp = (__nv_bfloat162*)&u;
            float2 g0 = __bfloat1622float2(bp[0]);
            float2 g1 = __bfloat1622float2(bp[1]);
            float2 g2 = __bfloat1622float2(bp[2]);
            float2 g3 = __bfloat1622float2(bp[3]);
            si[rr] = fmaf(g0.x, wi0.x, si[rr]); si[rr] = fmaf(g0.y, wi0.y, si[rr]);
            si[rr] = fmaf(g1.x, wi0.z, si[rr]); si[rr] = fmaf(g1.y, wi0.w, si[rr]);
            si[rr] = fmaf(g2.x, wi1.x, si[rr]); si[rr] = fmaf(g2.y, wi1.y, si[rr]);
            si[rr] = fmaf(g3.x, wi1.z, si[rr]); si[rr] = fmaf(g3.y, wi1.w, si[rr]);
            sf[rr] = fmaf(g0.x, wf0.x, sf[rr]); sf[rr] = fmaf(g0.y, wf0.y, sf[rr]);
            sf[rr] = fmaf(g1.x, wf0.z, sf[rr]); sf[rr] = fmaf(g1.y, wf0.w, sf[rr]);
            sf[rr] = fmaf(g2.x, wf1.x, sf[rr]); sf[rr] = fmaf(g2.y, wf1.y, sf[rr]);
            sf[rr] = fmaf(g3.x, wf1.z, sf[rr]); sf[rr] = fmaf(g3.y, wf1.w, sf[rr]);
        }
    }
#pragma unroll
    for (int off=16; off>0; off>>=1){
#pragma unroll
        for (int rr=0;rr<GROWS;rr++){
            si[rr] += __shfl_xor_sync(0xffffffffu, si[rr], off);
            sf[rr] += __shfl_xor_sync(0xffffffffu, sf[rr], off);
        }
    }
    if (lane == 0){
#pragma unroll
        for (int rr=0;rr<GROWS;rr++){
            g_ig[w*SEQ + l0+rr] = si[rr] + igb[w];
            g_fg[w*SEQ + l0+rr] = sf[rr] + fgb[w];
        }
    }
}

__global__ __launch_bounds__(256) void scan_kernel()
{
    __shared__ float lf[SEQ];
    __shared__ float tot[256];
    int h = blockIdx.x, tid = threadIdx.x;
    for (int m = tid; m < SEQ; m += 256){
        float f = g_fg[h*SEQ + m];
        lf[m] = fminf(f, 0.f) - log1pf(expf(-fabsf(f)));
    }
    __syncthreads();
    int base = tid * 8;
    float csl[8];
    float run = 0.f;
#pragma unroll
    for (int j=0;j<8;j++){ run += lf[base+j]; csl[j] = run; }
    tot[tid] = run; __syncthreads();
    for (int off=1; off<256; off<<=1){
        float v = (tid >= off) ? tot[tid-off] : 0.f;
        __syncthreads();
        tot[tid] += v;
        __syncthreads();
    }
    float excl = tot[tid] - run;
    float cs[8], cml[8];
    float rmax = -INFINITY;
#pragma unroll
    for (int j=0;j<8;j++){
        cs[j] = csl[j] + excl;
        float col = g_ig[h*SEQ + base + j] - cs[j];
        g_colt[h*SEQ + base + j] = col;
        rmax = fmaxf(rmax, col);
        cml[j] = rmax;
    }
    tot[tid] = rmax; __syncthreads();
    for (int off=1; off<256; off<<=1){
        float v = (tid >= off) ? tot[tid-off] : -INFINITY;
        __syncthreads();
        tot[tid] = fmaxf(tot[tid], v);
        __syncthreads();
    }
    float em = (tid > 0) ? tot[tid-1] : -INFINITY;
#pragma unroll
    for (int j=0;j<8;j++){
        float rm = fmaxf(em, cml[j]);
        g_rowt[h*SEQ + base + j] = -rm;
        g_expn[h*SEQ + base + j] = expf(-(cs[j] + rm));
    }
}

// group norm reading the two pav partial buffers
__global__ __launch_bounds__(256) void gn_kernel(const float* __restrict__ gnw,
    const float* __restrict__ gnb, const float* __restrict__ skip)
{
    int l = blockIdx.x, tid = threadIdx.x, w = tid >> 5, lane = tid & 31;
    int c0 = w*DHEAD + lane*8;
    float4 h0a = *(const float4*)(g_hfl  + (size_t)l*DIN + c0);
    float4 h1a = *(const float4*)(g_hfl  + (size_t)l*DIN + c0 + 4);
    float4 h0b = *(const float4*)(g_hfl2 + (size_t)l*DIN + c0);
    float4 h1b = *(const float4*)(g_hfl2 + (size_t)l*DIN + c0 + 4);
    float vals[8] = {h0a.x+h0b.x, h0a.y+h0b.y, h0a.z+h0b.z, h0a.w+h0b.w,
                     h1a.x+h1b.x, h1a.y+h1b.y, h1a.z+h1b.z, h1a.w+h1b.w};
    float s = 0.f, ss = 0.f;
#pragma unroll
    for (int j=0;j<8;j++){ s += vals[j]; ss += vals[j]*vals[j]; }
#pragma unroll
    for (int off=16; off>0; off>>=1){
        s  += __shfl_xor_sync(0xffffffffu, s,  off);
        ss += __shfl_xor_sync(0xffffffffu, ss, off);
    }
    float mean = s * (1.f/DHEAD);
    float var  = ss * (1.f/DHEAD) - mean*mean;
    float rstd = rsqrtf(var + 1e-5f);
    float4 gw0 = *(const float4*)(gnw + c0), gw1 = *(const float4*)(gnw + c0 + 4);
    float4 gb0 = *(const float4*)(gnb + c0), gb1 = *(const float4*)(gnb + c0 + 4);
    float4 sk0 = *(const float4*)(skip + c0), sk1 = *(const float4*)(skip + c0 + 4);
    uint4 uxc = *(const uint4*)(g_xc_bf + (size_t)l*DIN + c0);
    uint4 urs = *(const uint4*)(g_proj_bf + (size_t)l*(2*DIN) + DIN + c0);
    float gwv[8] = {gw0.x,gw0.y,gw0.z,gw0.w,gw1.x,gw1.y,gw1.z,gw1.w};
    float gbv[8] = {gb0.x,gb0.y,gb0.z,gb0.w,gb1.x,gb1.y,gb1.z,gb1.w};
    float skv[8] = {sk0.x,sk0.y,sk0.z,sk0.w,sk1.x,sk1.y,sk1.z,sk1.w};
    float xcv[8], rsv[8];
    {
        __nv_bfloat162* bx = (__nv_bfloat162*)&uxc;
        __nv_bfloat162* br = (__nv_bfloat162*)&urs;
#pragma unroll
        for (int j=0;j<4;j++){
            float2 fx = __bfloat1622float2(bx[j]); xcv[2*j]=fx.x; xcv[2*j+1]=fx.y;
            float2 fr = __bfloat1622float2(br[j]); rsv[2*j]=fr.x; rsv[2*j+1]=fr.y;
        }
    }
    __nv_bfloat162 o[4];
#pragma unroll
    for (int j=0;j<4;j++){
        float y0, y1;
        {
            float hn = (vals[2*j] - mean) * rstd;
            float h2 = hn*gwv[2*j] + gbv[2*j] + skv[2*j]*xcv[2*j];
            float r  = rsv[2*j];
            y0 = h2 * (r * fsigmoid(r));
        }
        {
            float hn = (vals[2*j+1] - mean) * rstd;
            float h2 = hn*gwv[2*j+1] + gbv[2*j+1] + skv[2*j+1]*xcv[2*j+1];
            float r  = rsv[2*j+1];
            y1 = h2 * (r * fsigmoid(r));
        }
        o[j] = __floats2bfloat162_rn(y0, y1);
    }
    *(uint4*)(g_yin_bf + (size_t)l*DIN + c0) = *(uint4*)o;
}

// ---------------- launch ----------------
extern "C" void kernel_launch(void* const* d_in, const int* in_sizes, int n_in,
                              void* d_out, int out_size)
{
    (void)in_sizes; (void)n_in; (void)out_size;
    const float* x    = (const float*)d_in[0];
    const float* ln1w = (const float*)d_in[2];
    const float* winw = (const float*)d_in[3];
    const float* winb = (const float*)d_in[4];
    const float* woutw= (const float*)d_in[5];
    const float* ck   = (const float*)d_in[6];
    const float* cb   = (const float*)d_in[7];
    const float* wq   = (const float*)d_in[8];
    const float* wk   = (const float*)d_in[9];
    const float* wv   = (const float*)d_in[10];
    const float* igw  = (const float*)d_in[11];
    const float* igb  = (const float*)d_in[12];
    const float* fgw  = (const float*)d_in[13];
    const float* fgb  = (const float*)d_in[14];
    const float* gnw  = (const float*)d_in[15];
    const float* gnb  = (const float*)d_in[16];
    const float* skip = (const float*)d_in[17];
    const float* ln2w = (const float*)d_in[18];
    const float* ffnw = (const float*)d_in[19];
    const float* ffnow= (const float*)d_in[20];
    float* out = (float*)d_out;

    static cudaStream_t s2;
    static cudaEvent_t evF, eWinw, eWt, eRest, eProj, eVt, eQK, eRes2;
    static int inited = 0;
    if (!inited){
        cudaStreamCreateWithFlags(&s2, cudaStreamNonBlocking);
        cudaEventCreateWithFlags(&evF,   cudaEventDisableTiming);
        cudaEventCreateWithFlags(&eWinw, cudaEventDisableTiming);
        cudaEventCreateWithFlags(&eWt,   cudaEventDisableTiming);
        cudaEventCreateWithFlags(&eRest, cudaEventDisableTiming);
        cudaEventCreateWithFlags(&eProj, cudaEventDisableTiming);
        cudaEventCreateWithFlags(&eVt,   cudaEventDisableTiming);
        cudaEventCreateWithFlags(&eQK,   cudaEventDisableTiming);
        cudaEventCreateWithFlags(&eRes2, cudaEventDisableTiming);
        cudaFuncSetAttribute(mma_nt_bf,    cudaFuncAttributeMaxDynamicSharedMemorySize, SMEM_GEMM);
        cudaFuncSetAttribute(mma_nt_sk,    cudaFuncAttributeMaxDynamicSharedMemorySize, SMEM_GEMM);
        cudaFuncSetAttribute(mma_ffn1,     cudaFuncAttributeMaxDynamicSharedMemorySize, SMEM_GEMM);
        cudaFuncSetAttribute(mma_qkv,      cudaFuncAttributeMaxDynamicSharedMemorySize, SMEM_GEMM);
        cudaFuncSetAttribute(mma_score_bf, cudaFuncAttributeMaxDynamicSharedMemorySize, SMEM_GEMM);
        cudaFuncSetAttribute(mma_pav_bf,   cudaFuncAttributeMaxDynamicSharedMemorySize, SMEM_GEMM);
        cudaFuncSetAttribute(gates_kernel, cudaFuncAttributeMaxDynamicSharedMemorySize, GROWS*3*DIN*2);
        inited = 1;
    }

    float *x2;
    bf16 *hln,*projb,*winwb,*yinb,*hfb,*g2b,*woutwb,*ffnowb;
    cudaGetSymbolAddress((void**)&x2,    g_x2);
    cudaGetSymbolAddress((void**)&hln,   g_hln_bf);
    cudaGetSymbolAddress((void**)&projb, g_proj_bf);
    cudaGetSymbolAddress((void**)&winwb, g_winw_bf);
    cudaGetSymbolAddress((void**)&yinb,  g_yin_bf);
    cudaGetSymbolAddress((void**)&hfb,   g_hf_bf);
    cudaGetSymbolAddress((void**)&g2b,   g_g2_bf);
    cudaGetSymbolAddress((void**)&woutwb, g_woutw_bf);
    cudaGetSymbolAddress((void**)&ffnowb, g_ffnow_bf);

    dim3 tb(32, 8);

    // ---- fork: weight prep on s2 ----
    cudaEventRecord(evF, 0);
    cudaStreamWaitEvent(s2, evF, 0);
    convert_winw<<<(CW_N0+255)/256, 256, 0, s2>>>(winw);
    cudaEventRecord(eWinw, s2);
    transpose_w_all<<<dim3(8,8,24), tb, 0, s2>>>(wq, wk, wv);
    cudaEventRecord(eWt, s2);
    convert_rest<<<(CW_N1+CW_N2+CW_N3+255)/256, 256, 0, s2>>>(woutw, ffnw, ffnow);
    cudaEventRecord(eRest, s2);

    // ---- main stream ----
    layernorm_bf<<<SEQ/8, 256>>>(x, ln1w, hln, DMOD);
    cudaStreamWaitEvent(0, eWinw, 0);
    // in-proj xi half (columns 0..2047) — critical path
    mma_nt_bf<<<dim3(DIN/BN, SEQ/BM), 256, SMEM_GEMM>>>(hln, winwb, winb, 0,
        (float*)0, projb, DMOD, DMOD, DMOD, 0, 0, 2*DIN);
    cudaEventRecord(eProj, 0);

    // s2: V GEMM + V transpose
    cudaStreamWaitEvent(s2, eProj, 0);
    mma_qkv<<<dim3(2, SEQ/BM, NHEAD), 256, SMEM_GEMM, s2>>>(2*NHEAD);   // v
    transpose_v_bf<<<dim3(SEQ/32, DHEAD/32, NHEAD), tb, 0, s2>>>();
    cudaEventRecord(eVt, s2);

    // main: conv, then q/k
    conv_silu_kernel<<<SEQ, 256>>>(ck, cb);
    cudaStreamWaitEvent(0, eWt, 0);
    mma_qkv<<<dim3(2, SEQ/BM, 2*NHEAD), 256, SMEM_GEMM>>>(0);           // q,k
    cudaEventRecord(eQK, 0);

    // s2: in-proj res half — fills the gates/scan bubble
    cudaStreamWaitEvent(s2, eQK, 0);
    mma_nt_bf<<<dim3(DIN/BN, SEQ/BM), 256, SMEM_GEMM, s2>>>(hln,
        winwb + (size_t)DIN*DMOD, winb + DIN, 0,
        (float*)0, projb + DIN, DMOD, DMOD, DMOD, 0, 0, 2*DIN);
    cudaEventRecord(eRes2, s2);

    // main: gates/scan
    cudaStreamWaitEvent(0, eVt, 0);
    gates_kernel<<<SEQ/GROWS, 256, GROWS*3*DIN*2>>>(igw, igb, fgw, fgb);
    scan_kernel<<<NHEAD, 256>>>();
    mma_score_bf<<<dim3(SEQ/BN, SEQ/BM, NHEAD), 256, SMEM_GEMM>>>();
    mma_pav_bf<<<dim3(2, SEQ/BM, 2*NHEAD), 256, SMEM_GEMM>>>();
    cudaStreamWaitEvent(0, eRes2, 0);
    gn_kernel<<<SEQ, 256>>>(gnw, gnb, skip);
    cudaStreamWaitEvent(0, eRest, 0);
    mma_nt_sk<<<dim3(DMOD/BN, SEQ/BM, 2), 256, SMEM_GEMM>>>(yinb, woutwb, DIN/2, DIN, DIN, 0);
    ln_combine<<<SEQ/8, 256>>>(x, ln2w, hfb, x2);
    mma_ffn1<<<dim3(4096/BN, SEQ/BM), 256, SMEM_GEMM>>>();
    mma_nt_sk<<<dim3(DMOD/BN, SEQ/BM, 2), 256, SMEM_GEMM>>>(g2b, ffnowb, DHID/2, DHID, DHID, 0);
    final_combine<<<SEQ*DMOD/4/256, 256>>>(out);
}

// round 17
// speedup vs baseline: 1.0457x; 1.0171x over previous
#include <cuda_runtime.h>
#include <cuda_bf16.h>
#include <math.h>

#define SEQ   2048
#define DMOD  1024
#define DIN   2048
#define NHEAD 8
#define DHEAD 256
#define DHID  2048

typedef __nv_bfloat16 bf16;

// ---------------- scratch (allocation-free: __device__ globals) ----------------
__device__ float g_ig  [NHEAD*SEQ];
__device__ float g_fg  [NHEAD*SEQ];
__device__ float g_rowt[NHEAD*SEQ];
__device__ float g_colt[NHEAD*SEQ];
__device__ float g_expn[NHEAD*SEQ];
__device__ float g_psum[NHEAD*16*SEQ];
__device__ float g_hfl [SEQ*DIN];
__device__ float g_hfl2[SEQ*DIN];
__device__ float g_x2  [SEQ*DMOD];
__device__ float g_sk0 [SEQ*DMOD];
__device__ float g_sk1 [SEQ*DMOD];

__device__ bf16 g_hln_bf [SEQ*DMOD];
__device__ bf16 g_proj_bf[SEQ*2*DIN];
__device__ bf16 g_xc_bf  [SEQ*DIN];
__device__ bf16 g_q_bf   [SEQ*DIN];
__device__ bf16 g_k_bf   [SEQ*DIN];
__device__ bf16 g_v_bf   [SEQ*DIN];
__device__ bf16 g_vt_bf  [(size_t)NHEAD*DHEAD*SEQ];
__device__ bf16 g_C_bf   [(size_t)NHEAD*SEQ*SEQ];
__device__ bf16 g_yin_bf [SEQ*DIN];
__device__ bf16 g_hf_bf  [SEQ*DMOD];
__device__ bf16 g_g2_bf  [SEQ*DHID];
__device__ bf16 g_winw_bf[2*DIN*DMOD];
__device__ bf16 g_woutw_bf[DMOD*DIN];
__device__ bf16 g_ffnw_bf[2*DHID*DMOD];   // ROW-REORDERED: row 2t = a-row t, row 2t+1 = z-row DHID+t
__device__ bf16 g_ffnow_bf[DMOD*DHID];
__device__ bf16 g_wqt_bf[NHEAD*DHEAD*DHEAD];
__device__ bf16 g_wkt_bf[NHEAD*DHEAD*DHEAD];
__device__ bf16 g_wvt_bf[NHEAD*DHEAD*DHEAD];

// ---------------- tile config ----------------
#define BM 128
#define BN 128
#define BKB 64                   // bf16 elements per stage (128B rows)
#define TILEB 16384              // 128 rows x 128B
#define SMEM_GEMM (6*TILEB)      // triple-buffered A+B = 96KB

__device__ __forceinline__ unsigned sw128(unsigned o){ return o ^ ((o>>3)&0x70); }

__device__ __forceinline__ void cp16(void* smem_dst, const void* gsrc){
    unsigned s = (unsigned)__cvta_generic_to_shared(smem_dst);
    asm volatile("cp.async.cg.shared.global [%0], [%1], 16;" :: "r"(s), "l"(gsrc));
}
#define CP_COMMIT() asm volatile("cp.async.commit_group;")
#define CP_WAIT(n)  asm volatile("cp.async.wait_group %0;" :: "n"(n))

__device__ __forceinline__ void ldsm4(unsigned r[4], const void* p){
    unsigned a = (unsigned)__cvta_generic_to_shared(p);
    asm volatile("ldmatrix.sync.aligned.m8n8.x4.shared.b16 {%0,%1,%2,%3}, [%4];"
        : "=r"(r[0]),"=r"(r[1]),"=r"(r[2]),"=r"(r[3]) : "r"(a));
}

#define MMA_BF16(d, a, b) \
  asm volatile("mma.sync.aligned.m16n8k16.row.col.f32.bf16.bf16.f32 " \
    "{%0,%1,%2,%3},{%4,%5,%6,%7},{%8,%9},{%0,%1,%2,%3};" \
    : "+f"((d)[0]),"+f"((d)[1]),"+f"((d)[2]),"+f"((d)[3]) \
    : "r"((a)[0]),"r"((a)[1]),"r"((a)[2]),"r"((a)[3]),"r"((b)[0]),"r"((b)[1]))

__device__ __forceinline__ float ftanh(float x){
    float y; asm("tanh.approx.f32 %0, %1;" : "=f"(y) : "f"(x)); return y;
}
__device__ __forceinline__ float fsigmoid(float x){ return 1.f / (1.f + __expf(-x)); }
__device__ __forceinline__ float fgelu(float a){
    float t = ftanh(0.7978845608028654f * (a + 0.044715f*a*a*a));
    return 0.5f * a * (1.f + t);
}

__device__ __forceinline__ void stage_bf(const bf16* __restrict__ src, int ld,
      int row0, int k0, char* S, int tid)
{
#pragma unroll
    for (int it=0; it<4; it++){
        int idx = it*256 + tid;
        int r = idx>>3, ch = idx&7;
        cp16(S + sw128(r*128 + ch*16), src + (size_t)(row0+r)*ld + k0 + ch*8);
    }
}

__device__ __forceinline__ void compute_bf(const char* __restrict__ As,
    const char* __restrict__ Bs, float acc[4][4][4], int lane, int wm, int wn)
{
    const int l15 = lane&15, lh = lane>>4, l7 = lane&7, lb3 = (lane>>3)&1;
#pragma unroll
    for (int kk=0;kk<4;kk++){
        unsigned a[4][4];
#pragma unroll
        for (int mt=0;mt<4;mt++)
            ldsm4(a[mt], As + sw128((wm + mt*16 + l15)*128 + (kk*2 + lh)*16));
        unsigned b[2][4];
#pragma unroll
        for (int bp=0;bp<2;bp++){
            unsigned row = wn + bp*16 + lh*8 + l7;
            ldsm4(b[bp], Bs + sw128(row*128 + (kk*2 + lb3)*16));
        }
#pragma unroll
        for (int mt=0;mt<4;mt++)
#pragma unroll
            for (int nt=0;nt<4;nt++)
                MMA_BF16(acc[mt][nt], a[mt], b[nt>>1] + (nt&1)*2);
    }
}

// 3-stage cp.async pipeline, one barrier per K-step
__device__ __forceinline__ void gemm_loop_bf(const bf16* __restrict__ A, int lda,
    const bf16* __restrict__ B, int ldb, int m0, int n0, int K,
    char* smem, float acc[4][4][4], int tid, int lane, int wm, int wn)
{
    const int nsteps = K >> 6;
    stage_bf(A, lda, m0, 0, smem, tid);
    stage_bf(B, ldb, n0, 0, smem + TILEB, tid);
    CP_COMMIT();
    if (nsteps > 1){
        stage_bf(A, lda, m0, BKB, smem + 2*TILEB, tid);
        stage_bf(B, ldb, n0, BKB, smem + 3*TILEB, tid);
        CP_COMMIT();
    }
    for (int s=0; s<nsteps; s++){
        if (s+1 < nsteps) { CP_WAIT(1); } else { CP_WAIT(0); }
        __syncthreads();
        if (s+2 < nsteps){
            char* T = smem + ((s+2)%3)*2*TILEB;
            stage_bf(A, lda, m0, (s+2)*BKB, T, tid);
            stage_bf(B, ldb, n0, (s+2)*BKB, T + TILEB, tid);
            CP_COMMIT();
        }
        char* Cur = smem + (s%3)*2*TILEB;
        compute_bf(Cur, Cur + TILEB, acc, lane, wm, wn);
    }
    __syncthreads();   // smem safe for reuse after loop
}

// ---------------- GEMM kernels ----------------

// C[m,n] = sum_k A[m,k]*B[n,k] (+bias) (+resid); optional fp32 out, optional bf16 out
__global__ __launch_bounds__(256, 2) void mma_nt_bf(
    const bf16* __restrict__ A, const bf16* __restrict__ B,
    const float* __restrict__ bias, const float* __restrict__ resid,
    float* __restrict__ Cf, bf16* __restrict__ Cb,
    int K, int lda, int ldb, int ldc, int ldr, int ldcb)
{
    extern __shared__ char smem[];
    const int tid=threadIdx.x, lane=tid&31, wid=tid>>5;
    const int wm=(wid>>2)*64, wn=(wid&3)*32;
    const int m0=blockIdx.y*BM, n0=blockIdx.x*BN;
    float acc[4][4][4] = {};
    gemm_loop_bf(A, lda, B, ldb, m0, n0, K, smem, acc, tid, lane, wm, wn);
    const int gr=lane>>2, gc=lane&3;
#pragma unroll
    for (int mt=0;mt<4;mt++){
#pragma unroll
        for (int nt=0;nt<4;nt++){
            int row = m0+wm+mt*16+gr;
            int col = n0+wn+nt*8+gc*2;
            float b0=0.f,b1=0.f;
            if (bias){ b0=bias[col]; b1=bias[col+1]; }
            float r00=0,r01=0,r10=0,r11=0;
            if (resid){
                const float* rp  = resid + (size_t)row*ldr + col;
                const float* rp2 = resid + (size_t)(row+8)*ldr + col;
                r00=rp[0]; r01=rp[1]; r10=rp2[0]; r11=rp2[1];
            }
            float v00=acc[mt][nt][0]+b0+r00, v01=acc[mt][nt][1]+b1+r01;
            float v10=acc[mt][nt][2]+b0+r10, v11=acc[mt][nt][3]+b1+r11;
            if (Cf){
                *(float2*)(Cf + (size_t)row*ldc + col)     = make_float2(v00,v01);
                *(float2*)(Cf + (size_t)(row+8)*ldc + col) = make_float2(v10,v11);
            }
            if (Cb){
                *(__nv_bfloat162*)(Cb + (size_t)row*ldcb + col)     = __floats2bfloat162_rn(v00,v01);
                *(__nv_bfloat162*)(Cb + (size_t)(row+8)*ldcb + col) = __floats2bfloat162_rn(v10,v11);
            }
        }
    }
}

// split-K NT GEMM with M-base: kidx selects K-half + output buffer; mbase offsets rows
__global__ __launch_bounds__(256, 2) void mma_nt_sk(
    const bf16* __restrict__ A, const bf16* __restrict__ B,
    int Khalf, int lda, int ldb, int mbase)
{
    extern __shared__ char smem[];
    const int tid=threadIdx.x, lane=tid&31, wid=tid>>5;
    const int wm=(wid>>2)*64, wn=(wid&3)*32;
    const int m0=(blockIdx.y + mbase)*BM, n0=blockIdx.x*BN;
    const int kidx = blockIdx.z;
    const int koff = kidx * Khalf;
    float* P = kidx ? g_sk1 : g_sk0;
    float acc[4][4][4] = {};
    gemm_loop_bf(A + koff, lda, B + koff, ldb, m0, n0, Khalf, smem, acc, tid, lane, wm, wn);
    const int gr=lane>>2, gc=lane&3;
#pragma unroll
    for (int mt=0;mt<4;mt++){
#pragma unroll
        for (int nt=0;nt<4;nt++){
            int row = m0+wm+mt*16+gr;
            int col = n0+wn+nt*8+gc*2;
            *(float2*)(P + (size_t)row*DMOD + col)     = make_float2(acc[mt][nt][0],acc[mt][nt][1]);
            *(float2*)(P + (size_t)(row+8)*DMOD + col) = make_float2(acc[mt][nt][2],acc[mt][nt][3]);
        }
    }
}

// ffn-in GEMM with fused GELU-pair epilogue (interleaved weights); mbase offsets rows.
__global__ __launch_bounds__(256, 2) void mma_ffn1(int mbase)
{
    extern __shared__ char smem[];
    const int tid=threadIdx.x, lane=tid&31, wid=tid>>5;
    const int wm=(wid>>2)*64, wn=(wid&3)*32;
    const int m0=(blockIdx.y + mbase)*BM, n0=blockIdx.x*BN;
    float acc[4][4][4] = {};
    gemm_loop_bf(g_hf_bf, DMOD, g_ffnw_bf, DMOD, m0, n0, DMOD, smem, acc, tid, lane, wm, wn);
    const int gr=lane>>2, gc=lane&3;
#pragma unroll
    for (int mt=0;mt<4;mt++){
#pragma unroll
        for (int nt=0;nt<4;nt++){
            int row = m0+wm+mt*16+gr;
            int col = n0+wn+nt*8+gc*2;   // even: a, odd: z
            int t = col >> 1;
            g_g2_bf[(size_t)row*DHID + t]     = __float2bfloat16_rn(fgelu(acc[mt][nt][0]) * acc[mt][nt][1]);
            g_g2_bf[(size_t)(row+8)*DHID + t] = __float2bfloat16_rn(fgelu(acc[mt][nt][2]) * acc[mt][nt][3]);
        }
    }
}

// fused q/k/v with z-base: z = blockIdx.z + zbase; which = z>>3 (0=q,1=k,2=v)
__global__ __launch_bounds__(256, 2) void mma_qkv(int zbase)
{
    const int z = blockIdx.z + zbase;
    const int which = z >> 3;
    const int h = z & 7;
    const bf16* A; int lda; const bf16* B; bf16* C;
    if (which == 0){ A = g_xc_bf   + h*DHEAD; lda = DIN;   B = g_wqt_bf + h*DHEAD*DHEAD; C = g_q_bf + h*DHEAD; }
    else if (which == 1){ A = g_xc_bf + h*DHEAD; lda = DIN; B = g_wkt_bf + h*DHEAD*DHEAD; C = g_k_bf + h*DHEAD; }
    else { A = g_proj_bf + h*DHEAD; lda = 2*DIN; B = g_wvt_bf + h*DHEAD*DHEAD; C = g_v_bf + h*DHEAD; }
    extern __shared__ char smem[];
    const int tid=threadIdx.x, lane=tid&31, wid=tid>>5;
    const int wm=(wid>>2)*64, wn=(wid&3)*32;
    const int m0=blockIdx.y*BM, n0=blockIdx.x*BN;
    float acc[4][4][4] = {};
    gemm_loop_bf(A, lda, B, DHEAD, m0, n0, DHEAD, smem, acc, tid, lane, wm, wn);
    const int gr=lane>>2, gc=lane&3;
#pragma unroll
    for (int mt=0;mt<4;mt++){
#pragma unroll
        for (int nt=0;nt<4;nt++){
            int row = m0+wm+mt*16+gr;
            int col = n0+wn+nt*8+gc*2;
            *(__nv_bfloat162*)(C + (size_t)row*DIN + col)     = __floats2bfloat162_rn(acc[mt][nt][0],acc[mt][nt][1]);
            *(__nv_bfloat162*)(C + (size_t)(row+8)*DIN + col) = __floats2bfloat162_rn(acc[mt][nt][2],acc[mt][nt][3]);
        }
    }
}

// scores: factorized decay epilogue (256 exps/CTA); bf16 out + fp32 tile row-sums
__global__ __launch_bounds__(256, 2) void mma_score_bf()
{
    const int h  = blockIdx.z;
    const int l0 = blockIdx.y * BM;
    const int m0 = blockIdx.x * BN;
    if (m0 >= l0 + BM) return;   // fully-masked tile: skipped (never read downstream)
    extern __shared__ char smem[];
    const bf16* A = g_q_bf + h*DHEAD;
    const bf16* B = g_k_bf + h*DHEAD;
    const int tid=threadIdx.x, lane=tid&31, wid=tid>>5;
    const int wm=(wid>>2)*64, wn=(wid&3)*32;
    float acc[4][4][4] = {};
    gemm_loop_bf(A, DIN, B, DIN, l0, m0, DHEAD, smem, acc, tid, lane, wm, wn);

    float* sred   = (float*)smem;        // 512 floats
    float* erow_s = sred + 512;          // 128 floats
    float* ecol_s = erow_s + 128;        // 128 floats
    const float* rt = g_rowt + h*SEQ;
    const float* ct = g_colt + h*SEQ;
    const float cref = ct[m0];
    if (tid < 128){
        erow_s[tid] = __expf(rt[l0 + tid] + cref);
    } else {
        int j = tid - 128;
        ecol_s[j] = __expf(ct[m0 + j] - cref);
    }
    __syncthreads();

    bf16* Cb = g_C_bf + (size_t)h*SEQ*SEQ;
    const int gr=lane>>2, gc=lane&3;
#pragma unroll
    for (int mt=0;mt<4;mt++){
        int lr = wm+mt*16+gr;
        int l = l0+lr;
        float rl0 = erow_s[lr]   * 0.0625f;
        float rl1 = erow_s[lr+8] * 0.0625f;
        float rs0 = 0.f, rs1 = 0.f;
#pragma unroll
        for (int nt=0;nt<4;nt++){
            int mc = wn+nt*8+gc*2;
            int m = m0+mc;
            float cm0 = ecol_s[mc], cm1 = ecol_s[mc+1];
            float v00 = (m   <= l  ) ? acc[mt][nt][0]*rl0*cm0 : 0.f;
            float v01 = (m+1 <= l  ) ? acc[mt][nt][1]*rl0*cm1 : 0.f;
            float v10 = (m   <= l+8) ? acc[mt][nt][2]*rl1*cm0 : 0.f;
            float v11 = (m+1 <= l+8) ? acc[mt][nt][3]*rl1*cm1 : 0.f;
            rs0 += v00 + v01;
            rs1 += v10 + v11;
            *(__nv_bfloat162*)(Cb + (size_t)l*SEQ + m)     = __floats2bfloat162_rn(v00,v01);
            *(__nv_bfloat162*)(Cb + (size_t)(l+8)*SEQ + m) = __floats2bfloat162_rn(v10,v11);
        }
        rs0 += __shfl_xor_sync(0xffffffffu, rs0, 1);
        rs0 += __shfl_xor_sync(0xffffffffu, rs0, 2);
        rs1 += __shfl_xor_sync(0xffffffffu, rs1, 1);
        rs1 += __shfl_xor_sync(0xffffffffu, rs1, 2);
        if (gc == 0){
            sred[(wm+mt*16+gr)*4   + (wid&3)] = rs0;
            sred[(wm+mt*16+gr+8)*4 + (wid&3)] = rs1;
        }
    }
    __syncthreads();
    if (tid < 128){
        float s = sred[tid*4] + sred[tid*4+1] + sred[tid*4+2] + sred[tid*4+3];
        g_psum[((size_t)h*16 + blockIdx.x)*SEQ + l0 + tid] = s;
    }
}

// hflat partials (split-K over the causal range): grid.z = sp*NHEAD + h
__global__ __launch_bounds__(256, 2) void mma_pav_bf()
{
    const int z  = blockIdx.z;
    const int sp = z >> 3;
    const int h  = z & 7;
    const int l0 = blockIdx.y * BM;
    const int n0 = blockIdx.x * BN;
    extern __shared__ char smem[];
    __shared__ float inrm_s[BM];
    const int tid=threadIdx.x, lane=tid&31, wid=tid>>5;
    if (tid < BM){
        int l = l0 + tid;
        int ntl = (l >> 7) + 1;
        float s = 0.f;
        for (int t=0; t<ntl; t++) s += g_psum[((size_t)h*16 + t)*SEQ + l];
        float n = fmaxf(fabsf(s), g_expn[h*SEQ + l]) + 1e-6f;
        inrm_s[tid] = 1.0f / n;
    }
    const int Kmax  = l0 + BM;
    const int Khalf = Kmax >> 1;
    const int k0 = sp ? Khalf : 0;
    const int Klen = sp ? (Kmax - Khalf) : Khalf;
    const bf16* A = g_C_bf + (size_t)h*SEQ*SEQ + k0;
    const bf16* B = g_vt_bf + (size_t)h*DHEAD*SEQ + k0;
    float* OUT = sp ? g_hfl2 : g_hfl;
    const int wm=(wid>>2)*64, wn=(wid&3)*32;
    float acc[4][4][4] = {};
    gemm_loop_bf(A, SEQ, B, SEQ, l0, n0, Klen, smem, acc, tid, lane, wm, wn);
    const int gr=lane>>2, gc=lane&3;
#pragma unroll
    for (int mt=0;mt<4;mt++){
#pragma unroll
        for (int nt=0;nt<4;nt++){
            int lr = wm+mt*16+gr;
            int l = l0+lr;
            int col = n0+wn+nt*8+gc*2;
            float s0 = inrm_s[lr];
            float s1 = inrm_s[lr+8];
            float* c0 = OUT + (size_t)l*DIN + h*DHEAD + col;
            float* c1 = OUT + (size_t)(l+8)*DIN + h*DHEAD + col;
            *(float2*)c0 = make_float2(acc[mt][nt][0]*s0, acc[mt][nt][1]*s0);
            *(float2*)c1 = make_float2(acc[mt][nt][2]*s1, acc[mt][nt][3]*s1);
        }
    }
}

// ---------------- weight prep ----------------
#define CW_N0 524288
#define CW_N1 262144
#define CW_N2 262144
#define CW_N3 524288
__device__ __forceinline__ void cvt8(const float* s, bf16* d){
    float4 a = ((const float4*)s)[0], b = ((const float4*)s)[1];
    __nv_bfloat162 o[4] = { __floats2bfloat162_rn(a.x,a.y), __floats2bfloat162_rn(a.z,a.w),
                            __floats2bfloat162_rn(b.x,b.y), __floats2bfloat162_rn(b.z,b.w) };
    *(uint4*)d = *(uint4*)o;
}
__global__ void convert_winw(const float* __restrict__ winw)
{
    int i = blockIdx.x*256 + threadIdx.x;
    if (i < CW_N0) cvt8(winw + (size_t)i*8, g_winw_bf + (size_t)i*8);
}
__global__ void convert_rest(const float* __restrict__ woutw,
                             const float* __restrict__ ffnw, const float* __restrict__ ffnow)
{
    int i = blockIdx.x*256 + threadIdx.x;
    if (i < CW_N1){
        cvt8(woutw + (size_t)i*8, g_woutw_bf + (size_t)i*8);
    } else if (i < CW_N1+CW_N2){
        int j = i - CW_N1;
        cvt8(ffnow + (size_t)j*8, g_ffnow_bf + (size_t)j*8);
    } else {
        int j = i - CW_N1 - CW_N2;
        if (j < CW_N3){
            int r = j >> 7, c8 = (j & 127) * 8;
            int src = (r & 1) ? (DHID + (r>>1)) : (r>>1);
            cvt8(ffnw + (size_t)src*DMOD + c8, g_ffnw_bf + (size_t)r*DMOD + c8);
        }
    }
}

__global__ void transpose_w_all(const float* __restrict__ wq, const float* __restrict__ wk,
                                const float* __restrict__ wv)
{
    __shared__ float t[32][33];
    int z = blockIdx.z;
    int which = z >> 3, h = z & 7;
    const float* I = (which==0 ? wq : which==1 ? wk : wv) + (size_t)h*DHEAD*DHEAD;
    bf16* O = (which==0 ? g_wqt_bf : which==1 ? g_wkt_bf : g_wvt_bf) + (size_t)h*DHEAD*DHEAD;
    int k0 = blockIdx.y*32, d0 = blockIdx.x*32;
    int x = threadIdx.x, y = threadIdx.y;
#pragma unroll
    for (int i=0;i<32;i+=8) t[y+i][x] = I[(size_t)(k0+y+i)*DHEAD + d0 + x];
    __syncthreads();
#pragma unroll
    for (int i=0;i<32;i+=8) O[(size_t)(d0+y+i)*DHEAD + k0 + x] = __float2bfloat16_rn(t[x][y+i]);
}

__global__ void transpose_v_bf()
{
    __shared__ float t[32][33];
    int h = blockIdx.z;
    int m0 = blockIdx.x*32, d0 = blockIdx.y*32;
    int x = threadIdx.x, y = threadIdx.y;
#pragma unroll
    for (int i=0;i<32;i+=8) t[y+i][x] = __bfloat162float(g_v_bf[(size_t)(m0+y+i)*DIN + h*DHEAD + d0 + x]);
    __syncthreads();
#pragma unroll
    for (int i=0;i<32;i+=8)
        g_vt_bf[((size_t)h*DHEAD + d0+y+i)*SEQ + m0 + x] = __float2bfloat16_rn(t[x][y+i]);
}

// ---------------- elementwise / reduction kernels ----------------
__global__ __launch_bounds__(256) void layernorm_bf(const float* __restrict__ x,
    const float* __restrict__ w, bf16* __restrict__ out, int cols)
{
    int wrp = threadIdx.x >> 5, lane = threadIdx.x & 31;
    int row = blockIdx.x*8 + wrp;
    const float* xr = x + (size_t)row*cols;
    float4 v[8];
    float s = 0.f, ss = 0.f;
#pragma unroll
    for (int i=0;i<8;i++){
        v[i] = ((const float4*)xr)[lane + i*32];
        s  += v[i].x + v[i].y + v[i].z + v[i].w;
        ss += v[i].x*v[i].x + v[i].y*v[i].y + v[i].z*v[i].z + v[i].w*v[i].w;
    }
#pragma unroll
    for (int off=16; off>0; off>>=1){
        s  += __shfl_xor_sync(0xffffffffu, s,  off);
        ss += __shfl_xor_sync(0xffffffffu, ss, off);
    }
    float mean = s / cols;
    float var  = ss / cols - mean*mean;
    float rstd = rsqrtf(var + 1e-5f);
    bf16* orow = out + (size_t)row*cols;
#pragma unroll
    for (int i=0;i<8;i++){
        float4 wv = ((const float4*)w)[lane + i*32];
        __nv_bfloat162 o0 = __floats2bfloat162_rn((v[i].x-mean)*rstd*wv.x, (v[i].y-mean)*rstd*wv.y);
        __nv_bfloat162 o1 = __floats2bfloat162_rn((v[i].z-mean)*rstd*wv.z, (v[i].w-mean)*rstd*wv.w);
        uint2 pk = make_uint2(*(unsigned*)&o0, *(unsigned*)&o1);
        *(uint2*)(orow + (lane + i*32)*4) = pk;
    }
}

// x2 = x + P0 + P1; hf = LN(x2)*w; bbase offsets block rows (M-pipelined)
__global__ __launch_bounds__(256) void ln_combine(const float* __restrict__ x,
    const float* __restrict__ w, bf16* __restrict__ out, float* __restrict__ x2, int bbase)
{
    const int cols = DMOD;
    int wrp = threadIdx.x >> 5, lane = threadIdx.x & 31;
    int row = (blockIdx.x + bbase)*8 + wrp;
    const float* xr = x + (size_t)row*cols;
    const float* p0 = g_sk0 + (size_t)row*cols;
    const float* p1 = g_sk1 + (size_t)row*cols;
    float4 v[8];
    float s = 0.f, ss = 0.f;
#pragma unroll
    for (int i=0;i<8;i++){
        float4 a = ((const float4*)xr)[lane + i*32];
        float4 b = ((const float4*)p0)[lane + i*32];
        float4 c = ((const float4*)p1)[lane + i*32];
        v[i] = make_float4(a.x+b.x+c.x, a.y+b.y+c.y, a.z+b.z+c.z, a.w+b.w+c.w);
        s  += v[i].x + v[i].y + v[i].z + v[i].w;
        ss += v[i].x*v[i].x + v[i].y*v[i].y + v[i].z*v[i].z + v[i].w*v[i].w;
    }
#pragma unroll
    for (int off=16; off>0; off>>=1){
        s  += __shfl_xor_sync(0xffffffffu, s,  off);
        ss += __shfl_xor_sync(0xffffffffu, ss, off);
    }
    float mean = s / cols;
    float var  = ss / cols - mean*mean;
    float rstd = rsqrtf(var + 1e-5f);
    bf16* orow = out + (size_t)row*cols;
    float* x2r = x2 + (size_t)row*cols;
#pragma unroll
    for (int i=0;i<8;i++){
        ((float4*)x2r)[lane + i*32] = v[i];
        float4 wv = ((const float4*)w)[lane + i*32];
        __nv_bfloat162 o0 = __floats2bfloat162_rn((v[i].x-mean)*rstd*wv.x, (v[i].y-mean)*rstd*wv.y);
        __nv_bfloat162 o1 = __floats2bfloat162_rn((v[i].z-mean)*rstd*wv.z, (v[i].w-mean)*rstd*wv.w);
        uint2 pk = make_uint2(*(unsigned*)&o0, *(unsigned*)&o1);
        *(uint2*)(orow + (lane + i*32)*4) = pk;
    }
}

// out = x2 + Q0 + Q1 (final split-K combine); ibase offsets float4 index (M-pipelined)
__global__ void final_combine(float* __restrict__ out, int ibase)
{
    int i = blockIdx.x*256 + threadIdx.x + ibase;
    float4 a = ((const float4*)g_x2)[i];
    float4 b = ((const float4*)g_sk0)[i];
    float4 c = ((const float4*)g_sk1)[i];
    ((float4*)out)[i] = make_float4(a.x+b.x+c.x, a.y+b.y+c.y, a.z+b.z+c.z, a.w+b.w+c.w);
}

__global__ __launch_bounds__(256) void conv_silu_kernel(const float* __restrict__ ck, const float* __restrict__ cb)
{
    int l = blockIdx.x;
    int c8 = threadIdx.x * 8;
    float acc[8];
    {
        float4 b0 = *(const float4*)(cb + c8);
        float4 b1 = *(const float4*)(cb + c8 + 4);
        acc[0]=b0.x; acc[1]=b0.y; acc[2]=b0.z; acc[3]=b0.w;
        acc[4]=b1.x; acc[5]=b1.y; acc[6]=b1.z; acc[7]=b1.w;
    }
    float4 kt[8];
#pragma unroll
    for (int j=0;j<8;j++) kt[j] = *(const float4*)(ck + (c8+j)*4);
#pragma unroll
    for (int t=0;t<4;t++){
        int ls = l - t;
        if (ls < 0) break;
        uint4 u = *(const uint4*)(g_proj_bf + (size_t)ls*(2*DIN) + c8);
        __nv_bfloat162* bp = (__nv_bfloat162*)&u;
        float tap[8];
#pragma unroll
        for (int j=0;j<4;j++){ float2 f = __bfloat1622float2(bp[j]); tap[2*j]=f.x; tap[2*j+1]=f.y; }
#pragma unroll
        for (int j=0;j<8;j++)
            acc[j] = fmaf(tap[j], ((float*)&kt[j])[t], acc[j]);
    }
    __nv_bfloat162 o[4];
#pragma unroll
    for (int j=0;j<4;j++){
        float a0 = acc[2*j],   r0 = a0 * fsigmoid(a0);
        float a1 = acc[2*j+1], r1 = a1 * fsigmoid(a1);
        o[j] = __floats2bfloat162_rn(r0, r1);
    }
    *(uint4*)(g_xc_bf + (size_t)l*DIN + c8) = *(uint4*)o;
}

#define GROWS 16
__global__ __launch_bounds__(256) void gates_kernel(
    const float* __restrict__ igw, const float* __restrict__ igb,
    const float* __restrict__ fgw, const float* __restrict__ fgb)
{
    extern __shared__ bf16 gbuf[];
    int l0 = blockIdx.x*GROWS, tid = threadIdx.x;
    const int CH = DIN/8;
    for (int i = tid; i < GROWS*3*CH; i += 256){
        int rr = i / (3*CH); int rem = i - rr*3*CH;
        int a = rem / CH;    int ch = rem - a*CH;
        const bf16* src = (a==0 ? g_q_bf : a==1 ? g_k_bf : g_v_bf) + (size_t)(l0+rr)*DIN + ch*8;
        *(uint4*)&gbuf[(size_t)rr*3*DIN + a*DIN + ch*8] = *(const uint4*)src;
    }
    __syncthreads();
    int w = tid >> 5, lane = tid & 31;
    const float* iw = igw + (size_t)w*3*DIN;
    const float* fw = fgw + (size_t)w*3*DIN;
    float si[GROWS] = {}, sf[GROWS] = {};
    for (int j = lane*8; j < 3*DIN; j += 256){
        float4 wi0 = *(const float4*)(iw + j), wi1 = *(const float4*)(iw + j + 4);
        float4 wf0 = *(const float4*)(fw + j), wf1 = *(const float4*)(fw + j + 4);
#pragma unroll
        for (int rr=0; rr<GROWS; rr++){
            uint4 u = *(uint4*)&gbuf[(size_t)rr*3*DIN + j];
            __nv_bfloat162* bp = (__nv_bfloat162*)&u;
            float2 g0 = __bfloat1622float2(bp[0]);
            float2 g1 = __bfloat1622float2(bp[1]);
            float2 g2 = __bfloat1622float2(bp[2]);
            float2 g3 = __bfloat1622float2(bp[3]);
            si[rr] = fmaf(g0.x, wi0.x, si[rr]); si[rr] = fmaf(g0.y, wi0.y, si[rr]);
            si[rr] = fmaf(g1.x, wi0.z, si[rr]); si[rr] = fmaf(g1.y, wi0.w, si[rr]);
            si[rr] = fmaf(g2.x, wi1.x, si[rr]); si[rr] = fmaf(g2.y, wi1.y, si[rr]);
            si[rr] = fmaf(g3.x, wi1.z, si[rr]); si[rr] = fmaf(g3.y, wi1.w, si[rr]);
            sf[rr] = fmaf(g0.x, wf0.x, sf[rr]); sf[rr] = fmaf(g0.y, wf0.y, sf[rr]);
            sf[rr] = fmaf(g1.x, wf0.z, sf[rr]); sf[rr] = fmaf(g1.y, wf0.w, sf[rr]);
            sf[rr] = fmaf(g2.x, wf1.x, sf[rr]); sf[rr] = fmaf(g2.y, wf1.y, sf[rr]);
            sf[rr] = fmaf(g3.x, wf1.z, sf[rr]); sf[rr] = fmaf(g3.y, wf1.w, sf[rr]);
        }
    }
#pragma unroll
    for (int off=16; off>0; off>>=1){
#pragma unroll
        for (int rr=0;rr<GROWS;rr++){
            si[rr] += __shfl_xor_sync(0xffffffffu, si[rr], off);
            sf[rr] += __shfl_xor_sync(0xffffffffu, sf[rr], off);
        }
    }
    if (lane == 0){
#pragma unroll
        for (int rr=0;rr<GROWS;rr++){
            g_ig[w*SEQ + l0+rr] = si[rr] + igb[w];
            g_fg[w*SEQ + l0+rr] = sf[rr] + fgb[w];
        }
    }
}

__global__ __launch_bounds__(256) void scan_kernel()
{
    __shared__ float lf[SEQ];
    __shared__ float tot[256];
    int h = blockIdx.x, tid = threadIdx.x;
    for (int m = tid; m < SEQ; m += 256){
        float f = g_fg[h*SEQ + m];
        lf[m] = fminf(f, 0.f) - log1pf(expf(-fabsf(f)));
    }
    __syncthreads();
    int base = tid * 8;
    float csl[8];
    float run = 0.f;
#pragma unroll
    for (int j=0;j<8;j++){ run += lf[base+j]; csl[j] = run; }
    tot[tid] = run; __syncthreads();
    for (int off=1; off<256; off<<=1){
        float v = (tid >= off) ? tot[tid-off] : 0.f;
        __syncthreads();
        tot[tid] += v;
        __syncthreads();
    }
    float excl = tot[tid] - run;
    float cs[8], cml[8];
    float rmax = -INFINITY;
#pragma unroll
    for (int j=0;j<8;j++){
        cs[j] = csl[j] + excl;
        float col = g_ig[h*SEQ + base + j] - cs[j];
        g_colt[h*SEQ + base + j] = col;
        rmax = fmaxf(rmax, col);
        cml[j] = rmax;
    }
    tot[tid] = rmax; __syncthreads();
    for (int off=1; off<256; off<<=1){
        float v = (tid >= off) ? tot[tid-off] : -INFINITY;
        __syncthreads();
        tot[tid] = fmaxf(tot[tid], v);
        __syncthreads();
    }
    float em = (tid > 0) ? tot[tid-1] : -INFINITY;
#pragma unroll
    for (int j=0;j<8;j++){
        float rm = fmaxf(em, cml[j]);
        g_rowt[h*SEQ + base + j] = -rm;
        g_expn[h*SEQ + base + j] = expf(-(cs[j] + rm));
    }
}

// group norm reading the two pav partial buffers
__global__ __launch_bounds__(256) void gn_kernel(const float* __restrict__ gnw,
    const float* __restrict__ gnb, const float* __restrict__ skip)
{
    int l = blockIdx.x, tid = threadIdx.x, w = tid >> 5, lane = tid & 31;
    int c0 = w*DHEAD + lane*8;
    float4 h0a = *(const float4*)(g_hfl  + (size_t)l*DIN + c0);
    float4 h1a = *(const float4*)(g_hfl  + (size_t)l*DIN + c0 + 4);
    float4 h0b = *(const float4*)(g_hfl2 + (size_t)l*DIN + c0);
    float4 h1b = *(const float4*)(g_hfl2 + (size_t)l*DIN + c0 + 4);
    float vals[8] = {h0a.x+h0b.x, h0a.y+h0b.y, h0a.z+h0b.z, h0a.w+h0b.w,
                     h1a.x+h1b.x, h1a.y+h1b.y, h1a.z+h1b.z, h1a.w+h1b.w};
    float s = 0.f, ss = 0.f;
#pragma unroll
    for (int j=0;j<8;j++){ s += vals[j]; ss += vals[j]*vals[j]; }
#pragma unroll
    for (int off=16; off>0; off>>=1){
        s  += __shfl_xor_sync(0xffffffffu, s,  off);
        ss += __shfl_xor_sync(0xffffffffu, ss, off);
    }
    float mean = s * (1.f/DHEAD);
    float var  = ss * (1.f/DHEAD) - mean*mean;
    float rstd = rsqrtf(var + 1e-5f);
    float4 gw0 = *(const float4*)(gnw + c0), gw1 = *(const float4*)(gnw + c0 + 4);
    float4 gb0 = *(const float4*)(gnb + c0), gb1 = *(const float4*)(gnb + c0 + 4);
    float4 sk0 = *(const float4*)(skip + c0), sk1 = *(const float4*)(skip + c0 + 4);
    uint4 uxc = *(const uint4*)(g_xc_bf + (size_t)l*DIN + c0);
    uint4 urs = *(const uint4*)(g_proj_bf + (size_t)l*(2*DIN) + DIN + c0);
    float gwv[8] = {gw0.x,gw0.y,gw0.z,gw0.w,gw1.x,gw1.y,gw1.z,gw1.w};
    float gbv[8] = {gb0.x,gb0.y,gb0.z,gb0.w,gb1.x,gb1.y,gb1.z,gb1.w};
    float skv[8] = {sk0.x,sk0.y,sk0.z,sk0.w,sk1.x,sk1.y,sk1.z,sk1.w};
    float xcv[8], rsv[8];
    {
        __nv_bfloat162* bx = (__nv_bfloat162*)&uxc;
        __nv_bfloat162* br = (__nv_bfloat162*)&urs;
#pragma unroll
        for (int j=0;j<4;j++){
            float2 fx = __bfloat1622float2(bx[j]); xcv[2*j]=fx.x; xcv[2*j+1]=fx.y;
            float2 fr = __bfloat1622float2(br[j]); rsv[2*j]=fr.x; rsv[2*j+1]=fr.y;
        }
    }
    __nv_bfloat162 o[4];
#pragma unroll
    for (int j=0;j<4;j++){
        float y0, y1;
        {
            float hn = (vals[2*j] - mean) * rstd;
            float h2 = hn*gwv[2*j] + gbv[2*j] + skv[2*j]*xcv[2*j];
            float r  = rsv[2*j];
            y0 = h2 * (r * fsigmoid(r));
        }
        {
            float hn = (vals[2*j+1] - mean) * rstd;
            float h2 = hn*gwv[2*j+1] + gbv[2*j+1] + skv[2*j+1]*xcv[2*j+1];
            float r  = rsv[2*j+1];
            y1 = h2 * (r * fsigmoid(r));
        }
        o[j] = __floats2bfloat162_rn(y0, y1);
    }
    *(uint4*)(g_yin_bf + (size_t)l*DIN + c0) = *(uint4*)o;
}

// ---------------- launch ----------------
extern "C" void kernel_launch(void* const* d_in, const int* in_sizes, int n_in,
                              void* d_out, int out_size)
{
    (void)in_sizes; (void)n_in; (void)out_size;
    const float* x    = (const float*)d_in[0];
    const float* ln1w = (const float*)d_in[2];
    const float* winw = (const float*)d_in[3];
    const float* winb = (const float*)d_in[4];
    const float* woutw= (const float*)d_in[5];
    const float* ck   = (const float*)d_in[6];
    const float* cb   = (const float*)d_in[7];
    const float* wq   = (const float*)d_in[8];
    const float* wk   = (const float*)d_in[9];
    const float* wv   = (const float*)d_in[10];
    const float* igw  = (const float*)d_in[11];
    const float* igb  = (const float*)d_in[12];
    const float* fgw  = (const float*)d_in[13];
    const float* fgb  = (const float*)d_in[14];
    const float* gnw  = (const float*)d_in[15];
    const float* gnb  = (const float*)d_in[16];
    const float* skip = (const float*)d_in[17];
    const float* ln2w = (const float*)d_in[18];
    const float* ffnw = (const float*)d_in[19];
    const float* ffnow= (const float*)d_in[20];
    float* out = (float*)d_out;

    static cudaStream_t s2;
    static cudaEvent_t evF, eWinw, eWt, eRest, eProj, eVt, eQK, eRes2, eW0, eFin0;
    static int inited = 0;
    if (!inited){
        cudaStreamCreateWithFlags(&s2, cudaStreamNonBlocking);
        cudaEventCreateWithFlags(&evF,   cudaEventDisableTiming);
        cudaEventCreateWithFlags(&eWinw, cudaEventDisableTiming);
        cudaEventCreateWithFlags(&eWt,   cudaEventDisableTiming);
        cudaEventCreateWithFlags(&eRest, cudaEventDisableTiming);
        cudaEventCreateWithFlags(&eProj, cudaEventDisableTiming);
        cudaEventCreateWithFlags(&eVt,   cudaEventDisableTiming);
        cudaEventCreateWithFlags(&eQK,   cudaEventDisableTiming);
        cudaEventCreateWithFlags(&eRes2, cudaEventDisableTiming);
        cudaEventCreateWithFlags(&eW0,   cudaEventDisableTiming);
        cudaEventCreateWithFlags(&eFin0, cudaEventDisableTiming);
        cudaFuncSetAttribute(mma_nt_bf,    cudaFuncAttributeMaxDynamicSharedMemorySize, SMEM_GEMM);
        cudaFuncSetAttribute(mma_nt_sk,    cudaFuncAttributeMaxDynamicSharedMemorySize, SMEM_GEMM);
        cudaFuncSetAttribute(mma_ffn1,     cudaFuncAttributeMaxDynamicSharedMemorySize, SMEM_GEMM);
        cudaFuncSetAttribute(mma_qkv,      cudaFuncAttributeMaxDynamicSharedMemorySize, SMEM_GEMM);
        cudaFuncSetAttribute(mma_score_bf, cudaFuncAttributeMaxDynamicSharedMemorySize, SMEM_GEMM);
        cudaFuncSetAttribute(mma_pav_bf,   cudaFuncAttributeMaxDynamicSharedMemorySize, SMEM_GEMM);
        cudaFuncSetAttribute(gates_kernel, cudaFuncAttributeMaxDynamicSharedMemorySize, GROWS*3*DIN*2);
        inited = 1;
    }

    float *x2;
    bf16 *hln,*projb,*winwb,*yinb,*hfb,*g2b,*woutwb,*ffnowb;
    cudaGetSymbolAddress((void**)&x2,    g_x2);
    cudaGetSymbolAddress((void**)&hln,   g_hln_bf);
    cudaGetSymbolAddress((void**)&projb, g_proj_bf);
    cudaGetSymbolAddress((void**)&winwb, g_winw_bf);
    cudaGetSymbolAddress((void**)&yinb,  g_yin_bf);
    cudaGetSymbolAddress((void**)&hfb,   g_hf_bf);
    cudaGetSymbolAddress((void**)&g2b,   g_g2_bf);
    cudaGetSymbolAddress((void**)&woutwb, g_woutw_bf);
    cudaGetSymbolAddress((void**)&ffnowb, g_ffnow_bf);

    dim3 tb(32, 8);

    // ---- fork: weight prep on s2 ----
    cudaEventRecord(evF, 0);
    cudaStreamWaitEvent(s2, evF, 0);
    convert_winw<<<(CW_N0+255)/256, 256, 0, s2>>>(winw);
    cudaEventRecord(eWinw, s2);
    transpose_w_all<<<dim3(8,8,24), tb, 0, s2>>>(wq, wk, wv);
    cudaEventRecord(eWt, s2);
    convert_rest<<<(CW_N1+CW_N2+CW_N3+255)/256, 256, 0, s2>>>(woutw, ffnw, ffnow);
    cudaEventRecord(eRest, s2);

    // ---- main stream ----
    layernorm_bf<<<SEQ/8, 256>>>(x, ln1w, hln, DMOD);
    cudaStreamWaitEvent(0, eWinw, 0);
    // in-proj xi half (columns 0..2047) — critical path
    mma_nt_bf<<<dim3(DIN/BN, SEQ/BM), 256, SMEM_GEMM>>>(hln, winwb, winb, 0,
        (float*)0, projb, DMOD, DMOD, DMOD, 0, 0, 2*DIN);
    cudaEventRecord(eProj, 0);

    // s2: V GEMM + V transpose
    cudaStreamWaitEvent(s2, eProj, 0);
    mma_qkv<<<dim3(2, SEQ/BM, NHEAD), 256, SMEM_GEMM, s2>>>(2*NHEAD);   // v
    transpose_v_bf<<<dim3(SEQ/32, DHEAD/32, NHEAD), tb, 0, s2>>>();
    cudaEventRecord(eVt, s2);

    // main: conv, then q/k
    conv_silu_kernel<<<SEQ, 256>>>(ck, cb);
    cudaStreamWaitEvent(0, eWt, 0);
    mma_qkv<<<dim3(2, SEQ/BM, 2*NHEAD), 256, SMEM_GEMM>>>(0);           // q,k
    cudaEventRecord(eQK, 0);

    // s2: in-proj res half — fills the gates/scan bubble
    cudaStreamWaitEvent(s2, eQK, 0);
    mma_nt_bf<<<dim3(DIN/BN, SEQ/BM), 256, SMEM_GEMM, s2>>>(hln,
        winwb + (size_t)DIN*DMOD, winb + DIN, 0,
        (float*)0, projb + DIN, DMOD, DMOD, DMOD, 0, 0, 2*DIN);
    cudaEventRecord(eRes2, s2);

    // main: gates/scan
    cudaStreamWaitEvent(0, eVt, 0);
    gates_kernel<<<SEQ/GROWS, 256, GROWS*3*DIN*2>>>(igw, igb, fgw, fgb);
    scan_kernel<<<NHEAD, 256>>>();
    mma_score_bf<<<dim3(SEQ/BN, SEQ/BM, NHEAD), 256, SMEM_GEMM>>>();
    mma_pav_bf<<<dim3(2, SEQ/BM, 2*NHEAD), 256, SMEM_GEMM>>>();
    cudaStreamWaitEvent(0, eRes2, 0);
    gn_kernel<<<SEQ, 256>>>(gnw, gnb, skip);
    cudaStreamWaitEvent(0, eRest, 0);

    // ---- M-pipelined FFN tail: M0 (rows 0-1023) on s2, M1 (rows 1024-2047) on main ----
    // wout M0 then M1 on main (s2 picks up M0 chain after eW0)
    mma_nt_sk<<<dim3(DMOD/BN, 8, 2), 256, SMEM_GEMM>>>(yinb, woutwb, DIN/2, DIN, DIN, 0);
    cudaEventRecord(eW0, 0);
    mma_nt_sk<<<dim3(DMOD/BN, 8, 2), 256, SMEM_GEMM>>>(yinb, woutwb, DIN/2, DIN, DIN, 8);

    // s2: M0 chain
    cudaStreamWaitEvent(s2, eW0, 0);
    ln_combine<<<128, 256, 0, s2>>>(x, ln2w, hfb, x2, 0);
    mma_ffn1<<<dim3(4096/BN, 8), 256, SMEM_GEMM, s2>>>(0);
    mma_nt_sk<<<dim3(DMOD/BN, 8, 2), 256, SMEM_GEMM, s2>>>(g2b, ffnowb, DHID/2, DHID, DHID, 0);
    final_combine<<<1024, 256, 0, s2>>>(out, 0);
    cudaEventRecord(eFin0, s2);

    // main: M1 chain
    ln_combine<<<128, 256>>>(x, ln2w, hfb, x2, 128);
    mma_ffn1<<<dim3(4096/BN, 8), 256, SMEM_GEMM>>>(8);
    mma_nt_sk<<<dim3(DMOD/BN, 8, 2), 256, SMEM_GEMM>>>(g2b, ffnowb, DHID/2, DHID, DHID, 8);
    final_combine<<<1024, 256>>>(out, 262144);

    // join
    cudaStreamWaitEvent(0, eFin0, 0);
}